// round 7
// baseline (speedup 1.0000x reference)
#include <cuda_runtime.h>
#include <cuda_fp16.h>
#include <math.h>
#include <stdint.h>

#define GN 4096
#define UN 100000
#define IN_ 8192
#define FN 128
#define MN 8192
#define NNZ_RUI 500000
#define NNZ_RGU 8192
#define NNZ_RGI 200000
#define SPLIT 8
#define MCH (MN / SPLIT)

// ---------------- scratch (device globals) ----------------------------------
__device__ float  g_rui_ei[(size_t)UN * FN];
__device__ float  g_rgu_t [(size_t)UN * FN];
__device__ float  g_rgi_t [(size_t)IN_ * FN];
__device__ float  g_rui_t [(size_t)IN_ * FN];
__device__ float  g_rgi_ei[(size_t)GN * FN];
__device__ float  g_rgu_eu[(size_t)GN * FN];
__device__ float  g_att_g [(size_t)GN * FN];
__device__ float  g_attitem[(size_t)IN_ * FN];
__device__ float  g_part[(size_t)SPLIT * IN_ * FN];
__device__ float  g_sum[MN];
__device__ __half g_members_h[(size_t)MN * FN];
__device__ __half g_item_h[(size_t)IN_ * FN];
__device__ __half g_bmat[(size_t)MN * FN];
__device__ __half g_S[(size_t)MN * IN_];
__device__ __half g_Wu_h[5 * FN * FN];
__device__ __half g_Wi_h[5 * FN * FN];
__device__ __half g_Wg_h[5 * FN * FN];

// ---------------- helpers ----------------------------------------------------
__device__ __forceinline__ uint32_t s2u(const void* p) {
    uint32_t a;
    asm("{ .reg .u64 t; cvta.to.shared.u64 t, %1; cvt.u32.u64 %0, t; }"
        : "=r"(a) : "l"(p));
    return a;
}
__device__ __forceinline__ void ldsm4(uint32_t* r, uint32_t addr) {
    asm volatile("ldmatrix.sync.aligned.m8n8.x4.shared.b16 {%0,%1,%2,%3}, [%4];"
                 : "=r"(r[0]), "=r"(r[1]), "=r"(r[2]), "=r"(r[3]) : "r"(addr));
}
__device__ __forceinline__ void ldsm4t(uint32_t* r, uint32_t addr) {
    asm volatile("ldmatrix.sync.aligned.m8n8.x4.trans.shared.b16 {%0,%1,%2,%3}, [%4];"
                 : "=r"(r[0]), "=r"(r[1]), "=r"(r[2]), "=r"(r[3]) : "r"(addr));
}
__device__ __forceinline__ void mma16(float* c, const uint32_t* a, const uint32_t* b) {
    asm volatile(
        "mma.sync.aligned.m16n8k16.row.col.f32.f16.f16.f32 "
        "{%0,%1,%2,%3},{%4,%5,%6,%7},{%8,%9},{%0,%1,%2,%3};"
        : "+f"(c[0]), "+f"(c[1]), "+f"(c[2]), "+f"(c[3])
        : "r"(a[0]), "r"(a[1]), "r"(a[2]), "r"(a[3]), "r"(b[0]), "r"(b[1]));
}
__device__ __forceinline__ void red4(float* o, float x, float y, float z, float w) {
    asm volatile("red.global.add.v4.f32 [%0], {%1,%2,%3,%4};"
                 :: "l"(o), "f"(x), "f"(y), "f"(z), "f"(w) : "memory");
}
__device__ __forceinline__ float pexp(float x) {
    float r = 2.7557319e-6f;
    r = fmaf(r, x, 2.4801587e-5f);
    r = fmaf(r, x, 1.9841270e-4f);
    r = fmaf(r, x, 1.3888889e-3f);
    r = fmaf(r, x, 8.3333333e-3f);
    r = fmaf(r, x, 4.1666667e-2f);
    r = fmaf(r, x, 1.6666667e-1f);
    r = fmaf(r, x, 0.5f);
    r = fmaf(r, x, 1.0f);
    r = fmaf(r, x, 1.0f);
    return r;
}
__device__ __forceinline__ uint32_t h2u(__half2 h) { return *(uint32_t*)&h; }
__device__ __forceinline__ uint4 f8_to_h8(float4 v0, float4 v1) {
    uint4 o;
    o.x = h2u(__floats2half2_rn(v0.x, v0.y));
    o.y = h2u(__floats2half2_rn(v0.z, v0.w));
    o.z = h2u(__floats2half2_rn(v1.x, v1.y));
    o.w = h2u(__floats2half2_rn(v1.z, v1.w));
    return o;
}
__device__ __forceinline__ uint4 hmul8(uint4 a, uint4 b) {
    uint4 o;
    o.x = h2u(__hmul2(*(__half2*)&a.x, *(__half2*)&b.x));
    o.y = h2u(__hmul2(*(__half2*)&a.y, *(__half2*)&b.y));
    o.z = h2u(__hmul2(*(__half2*)&a.z, *(__half2*)&b.z));
    o.w = h2u(__hmul2(*(__half2*)&a.w, *(__half2*)&b.w));
    return o;
}

// =============== fat0: all fp32->fp16 conversions + member gather =============
__global__ __launch_bounds__(256) void fat0_k(
    const float* __restrict__ user, const int* __restrict__ idx,
    const float* __restrict__ item,
    const float* __restrict__ Wu, const float* __restrict__ Wi,
    const float* __restrict__ Wg) {
    int bid = blockIdx.x;
    int t = (bid & 511) * 256 + threadIdx.x;  // local index for first two groups
    if (bid < 512) {                          // gather members
        int m = t >> 4, j = t & 15;
        const float* src = user + (size_t)idx[m] * FN + j * 8;
        ((uint4*)g_members_h)[t] =
            f8_to_h8(*(const float4*)src, *(const float4*)(src + 4));
    } else if (bid < 1024) {                  // item conv
        float4 v0 = ((const float4*)item)[t * 2];
        float4 v1 = ((const float4*)item)[t * 2 + 1];
        ((uint4*)g_item_h)[t] = f8_to_h8(v0, v1);
    } else {                                  // W convs: 40 CTAs each
        int g = (bid - 1024) / 40, lb = (bid - 1024) % 40;
        int u = lb * 256 + threadIdx.x;
        if (u < 10240) {
            const float* src = g == 0 ? Wu : (g == 1 ? Wi : Wg);
            __half* dst = g == 0 ? g_Wu_h : (g == 1 ? g_Wi_h : g_Wg_h);
            float4 v0 = ((const float4*)src)[u * 2];
            float4 v1 = ((const float4*)src)[u * 2 + 1];
            ((uint4*)dst)[u] = f8_to_h8(v0, v1);
        }
    }
}

// =============== GEMM1 body (fp16 mma) + exp + row-sum ========================
#define PIT 40
__device__ void gemm_s_body(char* sm, int bx, int by) {
    __half* As = (__half*)sm;
    __half* Bs = (__half*)(sm + 10240);
    float(*rs)[4] = (float(*)[4])(sm + 20480);
    int bm = by * 128, bn = bx * 128;
    int tid = threadIdx.x, lane = tid & 31, warp = tid >> 5;
    int wm = warp >> 2, wn = warp & 3;
    int qr = lane >> 2, qc = lane & 3;
    int q = lane >> 3, r = lane & 7;
    uint32_t abase = s2u(As), bbase = s2u(Bs);
    float acc[4][4][4];
#pragma unroll
    for (int i = 0; i < 4; i++)
#pragma unroll
        for (int j = 0; j < 4; j++)
#pragma unroll
            for (int c = 0; c < 4; c++) acc[i][j][c] = 0.f;

#pragma unroll
    for (int k0 = 0; k0 < FN; k0 += 32) {
#pragma unroll
        for (int it = 0; it < 2; ++it) {
            int ch = tid + it * 256;
            int row = ch >> 2, c8 = (ch & 3) * 8;
            *(uint4*)&As[row * PIT + c8] =
                *(const uint4*)(g_members_h + (size_t)(bm + row) * FN + k0 + c8);
            *(uint4*)&Bs[row * PIT + c8] =
                *(const uint4*)(g_item_h + (size_t)(bn + row) * FN + k0 + c8);
        }
        __syncthreads();
#pragma unroll
        for (int ks = 0; ks < 2; ++ks) {
            int kl = ks * 16 + (q >> 1) * 8;
            uint32_t a[4][4], b[4][2];
#pragma unroll
            for (int mi = 0; mi < 4; ++mi) {
                int arow = wm * 64 + mi * 16 + (q & 1) * 8 + r;
                ldsm4(a[mi], abase + (arow * PIT + kl) * 2);
            }
#pragma unroll
            for (int j = 0; j < 2; ++j) {
                int brow = wn * 32 + j * 16 + (q & 1) * 8 + r;
                uint32_t t[4];
                ldsm4(t, bbase + (brow * PIT + kl) * 2);
                b[j * 2][0] = t[0]; b[j * 2 + 1][0] = t[1];
                b[j * 2][1] = t[2]; b[j * 2 + 1][1] = t[3];
            }
#pragma unroll
            for (int mi = 0; mi < 4; ++mi)
#pragma unroll
                for (int ni = 0; ni < 4; ++ni) mma16(acc[mi][ni], a[mi], b[ni]);
        }
        __syncthreads();
    }
#pragma unroll
    for (int mi = 0; mi < 4; ++mi) {
        int r0 = wm * 64 + mi * 16 + qr;
        float s0 = 0.f, s1 = 0.f;
#pragma unroll
        for (int ni = 0; ni < 4; ++ni) {
            int col = bn + wn * 32 + ni * 8 + qc * 2;
            float e0 = pexp(acc[mi][ni][0]), e1 = pexp(acc[mi][ni][1]);
            float e2 = pexp(acc[mi][ni][2]), e3 = pexp(acc[mi][ni][3]);
            *(__half2*)(g_S + (size_t)(bm + r0) * IN_ + col) = __floats2half2_rn(e0, e1);
            *(__half2*)(g_S + (size_t)(bm + r0 + 8) * IN_ + col) = __floats2half2_rn(e2, e3);
            s0 += e0 + e1; s1 += e2 + e3;
        }
        s0 += __shfl_xor_sync(0xffffffffu, s0, 1);
        s0 += __shfl_xor_sync(0xffffffffu, s0, 2);
        s1 += __shfl_xor_sync(0xffffffffu, s1, 1);
        s1 += __shfl_xor_sync(0xffffffffu, s1, 2);
        if (qc == 0) { rs[r0][wn] = s0; rs[r0 + 8][wn] = s1; }
    }
    __syncthreads();
    if (tid < 128) {
        float s = rs[tid][0] + rs[tid][1] + rs[tid][2] + rs[tid][3];
        atomicAdd(&g_sum[bm + tid], s);
    }
}

// =============== dual COO scatter: out1[r]+=v*X1[c]; out2[c]+=v*X2[r] =========
__device__ __forceinline__ void spmm_dual_body(
    int w, const int* __restrict__ rows, const int* __restrict__ cols,
    const float* __restrict__ vals, const float* __restrict__ X1,
    float* __restrict__ out1, const float* __restrict__ X2,
    float* __restrict__ out2, int nnz, int lane) {
    if (w >= nnz) return;
    int r = rows[w], c = cols[w];
    float v = vals[w];
    float4 x1 = ((const float4*)(X1 + (size_t)c * FN))[lane];
    float4 x2 = ((const float4*)(X2 + (size_t)r * FN))[lane];
    red4(out1 + (size_t)r * FN + lane * 4, v * x1.x, v * x1.y, v * x1.z, v * x1.w);
    red4(out2 + (size_t)c * FN + lane * 4, v * x2.x, v * x2.y, v * x2.z, v * x2.w);
}

// =============== fat1: gemm_s tiles + 3 dual scatters, striped =================
// grid = 92620. specials (bid%16==0, 5789): sid<4096 gemm; <5120 rgu; else rgi-A(669)
// non-specials (86831): nsid<62500 rui; else rgi-B(24331)
__global__ __launch_bounds__(256) void fat1_k(
    const int* __restrict__ rui_r, const int* __restrict__ rui_c,
    const float* __restrict__ rui_v,
    const int* __restrict__ rgu_r, const int* __restrict__ rgu_c,
    const float* __restrict__ rgu_v,
    const int* __restrict__ rgi_r, const int* __restrict__ rgi_c,
    const float* __restrict__ rgi_v,
    const float* __restrict__ item, const float* __restrict__ user,
    const float* __restrict__ group) {
    extern __shared__ char sm[];
    int bid = blockIdx.x;
    int lane = threadIdx.x & 31, warp = threadIdx.x >> 5;
    if ((bid & 15) == 0) {
        int sid = bid >> 4;
        if (sid < 4096) {
            gemm_s_body(sm, sid & 63, sid >> 6);
        } else if (sid < 5120) {
            int w = (sid - 4096) * 8 + warp;
            spmm_dual_body(w, rgu_r, rgu_c, rgu_v, user, g_rgu_eu, group,
                           g_rgu_t, NNZ_RGU, lane);
        } else {
            int w = (sid - 5120) * 8 + warp;
            spmm_dual_body(w, rgi_r, rgi_c, rgi_v, item, g_rgi_ei, group,
                           g_rgi_t, NNZ_RGI, lane);
        }
    } else {
        int nsid = bid - (bid >> 4) - 1;
        if (nsid < 62500) {
            int w = nsid * 8 + warp;
            spmm_dual_body(w, rui_r, rui_c, rui_v, item, g_rui_ei, user,
                           g_rui_t, NNZ_RUI, lane);
        } else {
            int w = (669 + (nsid - 62500)) * 8 + warp;
            spmm_dual_body(w, rgi_r, rgi_c, rgi_v, item, g_rgi_ei, group,
                           g_rgi_t, NNZ_RGI, lane);
        }
    }
}

__global__ void inv_bmat_k() {
    int t = blockIdx.x * blockDim.x + threadIdx.x;
    if (t >= MN * 16) return;
    int m = t >> 4;
    float sc = 4096.0f / g_sum[m];
    uint4 v = ((const uint4*)g_members_h)[t];
    __half2 s2 = __float2half2_rn(sc);
    uint4 o;
    o.x = h2u(__hmul2(*(__half2*)&v.x, s2));
    o.y = h2u(__hmul2(*(__half2*)&v.y, s2));
    o.z = h2u(__hmul2(*(__half2*)&v.z, s2));
    o.w = h2u(__hmul2(*(__half2*)&v.w, s2));
    ((uint4*)g_bmat)[t] = o;
}

// =============== attn2 body (fp16 mma, split-K, ldmatrix.trans) ================
#define PIT2 136
__device__ void attn2_body(char* sm, int bx, int sp) {
    __half* Ssm = (__half*)sm;
    __half* Bsm = (__half*)(sm + 8704);
    int bi = bx * 128;
    int ms = sp * MCH;
    int tid = threadIdx.x, lane = tid & 31, warp = tid >> 5;
    int wm = warp >> 2, wn = warp & 3;
    int qr = lane >> 2, qc = lane & 3;
    int q = lane >> 3, r = lane & 7;
    uint32_t sbase = s2u(Ssm), bbase = s2u(Bsm);
    float acc[4][4][4];
#pragma unroll
    for (int i = 0; i < 4; i++)
#pragma unroll
        for (int j = 0; j < 4; j++)
#pragma unroll
            for (int c = 0; c < 4; c++) acc[i][j][c] = 0.f;

    for (int m0 = ms; m0 < ms + MCH; m0 += 32) {
#pragma unroll
        for (int it = 0; it < 2; ++it) {
            int ch = tid + it * 256;
            int mm = ch >> 4, c8 = (ch & 15) * 8;
            *(uint4*)&Ssm[mm * PIT2 + c8] =
                *(const uint4*)(g_S + (size_t)(m0 + mm) * IN_ + bi + c8);
            *(uint4*)&Bsm[mm * PIT2 + c8] =
                *(const uint4*)(g_bmat + (size_t)(m0 + mm) * FN + c8);
        }
        __syncthreads();
#pragma unroll
        for (int ks = 0; ks < 2; ++ks) {
            int k0l = ks * 16;
            uint32_t a[4][4], b[4][2];
#pragma unroll
            for (int mi = 0; mi < 4; ++mi) {
                int row = k0l + (q >> 1) * 8 + r;
                int col = wm * 64 + mi * 16 + (q & 1) * 8;
                ldsm4t(a[mi], sbase + (row * PIT2 + col) * 2);
            }
#pragma unroll
            for (int j = 0; j < 2; ++j) {
                int row = k0l + (q & 1) * 8 + r;
                int col = wn * 32 + j * 16 + (q >> 1) * 8;
                uint32_t t[4];
                ldsm4t(t, bbase + (row * PIT2 + col) * 2);
                b[j * 2][0] = t[0]; b[j * 2][1] = t[1];
                b[j * 2 + 1][0] = t[2]; b[j * 2 + 1][1] = t[3];
            }
#pragma unroll
            for (int mi = 0; mi < 4; ++mi)
#pragma unroll
                for (int ni = 0; ni < 4; ++ni) mma16(acc[mi][ni], a[mi], b[ni]);
        }
        __syncthreads();
    }
    float* dst = g_part + (size_t)sp * IN_ * FN;
#pragma unroll
    for (int mi = 0; mi < 4; ++mi) {
        int r0 = wm * 64 + mi * 16 + qr;
#pragma unroll
        for (int ni = 0; ni < 4; ++ni) {
            int col = wn * 32 + ni * 8 + qc * 2;
            float2 v01 = {acc[mi][ni][0], acc[mi][ni][1]};
            float2 v23 = {acc[mi][ni][2], acc[mi][ni][3]};
            *(float2*)(dst + (size_t)(bi + r0) * FN + col) = v01;
            *(float2*)(dst + (size_t)(bi + r0 + 8) * FN + col) = v23;
        }
    }
}

// =============== lin5 body (fp16 mma, fused epilogue) ==========================
// MODE 0 (user/item): xs = [e, a, a*e, b*e, b];  MODE 1 (group): [e, a, b*e, a*e, c]
template <int MODE>
__device__ void lin5_body(char* sm, int bm,
                          const float* __restrict__ E, const float* __restrict__ A,
                          const float* __restrict__ B, const float* __restrict__ C4,
                          const __half* __restrict__ Wh,
                          const float* __restrict__ bias,
                          float* __restrict__ out, int Md) {
    __half* raw = (__half*)sm;                    // 3 * 4096 halves
    __half* As = (__half*)(sm + 24576);
    __half* Bs = (__half*)(sm + 34816);
    float(*rs)[4] = (float(*)[4])(sm + 45056);
    float* bsum = (float*)(sm + 47104);
    int tid = threadIdx.x, lane = tid & 31, warp = tid >> 5;
    int wm = warp >> 2, wn = warp & 3;
    int qr = lane >> 2, qc = lane & 3;
    int q = lane >> 3, r = lane & 7;
    uint32_t abase = s2u(As), bbase = s2u(Bs);
    if (tid < 128)
        bsum[tid] = bias[tid] + bias[128 + tid] + bias[256 + tid] +
                    bias[384 + tid] + bias[512 + tid];
    float acc[4][4][4];
#pragma unroll
    for (int i = 0; i < 4; i++)
#pragma unroll
        for (int j = 0; j < 4; j++)
#pragma unroll
            for (int c = 0; c < 4; c++) acc[i][j][c] = 0.f;

    for (int fbi = 0; fbi < 4; ++fbi) {
        int fb = fbi * 32;
#pragma unroll
        for (int it = 0; it < 6; ++it) {
            int ch = tid + it * 256;
            int tilei = ch / 512, rem = ch & 511;
            int row = rem >> 2, c8 = (rem & 3) * 8;
            int m = bm + row;
            float4 v0 = {0.f, 0.f, 0.f, 0.f}, v1 = {0.f, 0.f, 0.f, 0.f};
            if (m < Md) {
                const float* src = tilei == 0 ? E : (tilei == 1 ? A : B);
                size_t off = (size_t)m * FN + fb + c8;
                v0 = *(const float4*)(src + off);
                v1 = *(const float4*)(src + off + 4);
            }
            *(uint4*)&raw[tilei * 4096 + row * 32 + c8] = f8_to_h8(v0, v1);
        }
        __syncthreads();
        for (int kblk = 0; kblk < 5; ++kblk) {
#pragma unroll
            for (int it = 0; it < 2; ++it) {
                int ch = tid + it * 256;
                int row = ch >> 2, c8 = (ch & 3) * 8;
                uint4 o;
                if (kblk == 0) o = *(const uint4*)&raw[row * 32 + c8];
                else if (kblk == 1) o = *(const uint4*)&raw[4096 + row * 32 + c8];
                else if (kblk == 2)
                    o = hmul8(*(const uint4*)&raw[(MODE == 0 ? 1 : 2) * 4096 + row * 32 + c8],
                              *(const uint4*)&raw[row * 32 + c8]);
                else if (kblk == 3)
                    o = hmul8(*(const uint4*)&raw[(MODE == 0 ? 2 : 1) * 4096 + row * 32 + c8],
                              *(const uint4*)&raw[row * 32 + c8]);
                else {
                    if (MODE == 0) o = *(const uint4*)&raw[2 * 4096 + row * 32 + c8];
                    else {
                        int m = bm + row;
                        float4 v0 = {0.f, 0.f, 0.f, 0.f}, v1 = v0;
                        if (m < Md) {
                            size_t off = (size_t)m * FN + fb + c8;
                            v0 = *(const float4*)(C4 + off);
                            v1 = *(const float4*)(C4 + off + 4);
                        }
                        o = f8_to_h8(v0, v1);
                    }
                }
                *(uint4*)&As[row * PIT + c8] = o;
                *(uint4*)&Bs[row * PIT + c8] =
                    *(const uint4*)(Wh + (size_t)kblk * 16384 + (size_t)row * FN + fb + c8);
            }
            __syncthreads();
#pragma unroll
            for (int ks = 0; ks < 2; ++ks) {
                int kl = ks * 16 + (q >> 1) * 8;
                uint32_t a[4][4], b[4][2];
#pragma unroll
                for (int mi = 0; mi < 4; ++mi) {
                    int arow = wm * 64 + mi * 16 + (q & 1) * 8 + r;
                    ldsm4(a[mi], abase + (arow * PIT + kl) * 2);
                }
#pragma unroll
                for (int j = 0; j < 2; ++j) {
                    int brow = wn * 32 + j * 16 + (q & 1) * 8 + r;
                    uint32_t t[4];
                    ldsm4(t, bbase + (brow * PIT + kl) * 2);
                    b[j * 2][0] = t[0]; b[j * 2 + 1][0] = t[1];
                    b[j * 2][1] = t[2]; b[j * 2 + 1][1] = t[3];
                }
#pragma unroll
                for (int mi = 0; mi < 4; ++mi)
#pragma unroll
                    for (int ni = 0; ni < 4; ++ni) mma16(acc[mi][ni], a[mi], b[ni]);
            }
            __syncthreads();
        }
    }
#pragma unroll
    for (int mi = 0; mi < 4; ++mi) {
        int r0 = wm * 64 + mi * 16 + qr;
        float s0 = 0.f, s1 = 0.f;
#pragma unroll
        for (int ni = 0; ni < 4; ++ni) {
            int col = wn * 32 + ni * 8 + qc * 2;
            float b0 = bsum[col], b1 = bsum[col + 1];
            float v0 = acc[mi][ni][0] + b0, v1 = acc[mi][ni][1] + b1;
            float v2 = acc[mi][ni][2] + b0, v3 = acc[mi][ni][3] + b1;
            v0 = v0 >= 0.f ? v0 : 0.01f * v0;
            v1 = v1 >= 0.f ? v1 : 0.01f * v1;
            v2 = v2 >= 0.f ? v2 : 0.01f * v2;
            v3 = v3 >= 0.f ? v3 : 0.01f * v3;
            acc[mi][ni][0] = v0; acc[mi][ni][1] = v1;
            acc[mi][ni][2] = v2; acc[mi][ni][3] = v3;
            s0 += v0 * v0 + v1 * v1;
            s1 += v2 * v2 + v3 * v3;
        }
        s0 += __shfl_xor_sync(0xffffffffu, s0, 1);
        s0 += __shfl_xor_sync(0xffffffffu, s0, 2);
        s1 += __shfl_xor_sync(0xffffffffu, s1, 1);
        s1 += __shfl_xor_sync(0xffffffffu, s1, 2);
        if (qc == 0) { rs[r0][wn] = s0; rs[r0 + 8][wn] = s1; }
    }
    __syncthreads();
#pragma unroll
    for (int mi = 0; mi < 4; ++mi) {
        int r0 = wm * 64 + mi * 16 + qr;
        float t0 = rs[r0][0] + rs[r0][1] + rs[r0][2] + rs[r0][3];
        float t1 = rs[r0 + 8][0] + rs[r0 + 8][1] + rs[r0 + 8][2] + rs[r0 + 8][3];
        float i0 = 1.0f / fmaxf(sqrtf(t0), 1e-12f);
        float i1 = 1.0f / fmaxf(sqrtf(t1), 1e-12f);
        int m0g = bm + r0, m1g = m0g + 8;
#pragma unroll
        for (int ni = 0; ni < 4; ++ni) {
            int col = wn * 32 + ni * 8 + qc * 2;
            if (m0g < Md) {
                float2 v = {acc[mi][ni][0] * i0, acc[mi][ni][1] * i0};
                *(float2*)(out + (size_t)m0g * FN + col) = v;
            }
            if (m1g < Md) {
                float2 v = {acc[mi][ni][2] * i1, acc[mi][ni][3] * i1};
                *(float2*)(out + (size_t)m1g * FN + col) = v;
            }
        }
    }
}

// =============== fat2: attn2 + lin5_user + lin5_item ===========================
// grid=1358: odd bids with h<512 -> attn2; rest -> lin5 user (782) then item (64)
__global__ __launch_bounds__(256) void fat2_k(
    const float* __restrict__ user_emb, const float* __restrict__ item_emb,
    const float* __restrict__ bu, const float* __restrict__ bi,
    float* __restrict__ out_u, float* __restrict__ out_i) {
    extern __shared__ char sm[];
    int bid = blockIdx.x;
    int h = bid >> 1;
    if ((bid & 1) && h < 512) {
        attn2_body(sm, h & 63, h >> 6);
    } else {
        int a = (bid + 1) >> 1;
        if (a > 512) a = 512;
        int rid = bid - a;
        if (rid < 782)
            lin5_body<0>(sm, rid * 128, user_emb, g_rui_ei, g_rgu_t, nullptr,
                         g_Wu_h, bu, out_u, UN);
        else
            lin5_body<0>(sm, (rid - 782) * 128, item_emb, g_rui_t, g_rgi_t,
                         nullptr, g_Wi_h, bi, out_i, IN_);
    }
}

__global__ __launch_bounds__(256) void lin5_group_k(
    const float* __restrict__ group_emb, const float* __restrict__ bg,
    float* __restrict__ out_g) {
    extern __shared__ char sm[];
    lin5_body<1>(sm, blockIdx.x * 128, group_emb, g_rgi_ei, g_rgu_eu, g_att_g,
                 g_Wg_h, bg, out_g, GN);
}

// =============== reduce partials * item * 2^-12 ================================
__global__ void attn2_reduce_k(const float* __restrict__ item) {
    int t = blockIdx.x * blockDim.x + threadIdx.x;
    if (t >= IN_ * FN / 4) return;
    float4 s = ((const float4*)g_part)[t];
#pragma unroll
    for (int sp = 1; sp < SPLIT; sp++) {
        float4 v = ((const float4*)(g_part + (size_t)sp * IN_ * FN))[t];
        s.x += v.x; s.y += v.y; s.z += v.z; s.w += v.w;
    }
    float4 e = ((const float4*)item)[t];
    const float c = 0.000244140625f;  // 2^-12
    s.x *= e.x * c; s.y *= e.y * c; s.z *= e.z * c; s.w *= e.w * c;
    ((float4*)g_attitem)[t] = s;
}

// =============== single COO scatter (att_g) ====================================
__global__ void spmm_k(const int* __restrict__ rows, const int* __restrict__ cols,
                       const float* __restrict__ vals, const float* __restrict__ X,
                       float* __restrict__ out, int nnz) {
    int w = (int)((blockIdx.x * 256u + threadIdx.x) >> 5);
    if (w >= nnz) return;
    int lane = threadIdx.x & 31;
    int r = rows[w], c = cols[w];
    float v = vals[w];
    float4 x = ((const float4*)(X + (size_t)c * FN))[lane];
    float* o = out + (size_t)r * FN + lane * 4;
    red4(o, v * x.x, v * x.y, v * x.z, v * x.w);
}

// =============== launch =========================================================
extern "C" void kernel_launch(void* const* d_in, const int* in_sizes, int n_in,
                              void* d_out, int out_size) {
    const float* group_emb = (const float*)d_in[0];
    const float* user_emb  = (const float*)d_in[1];
    const float* item_emb  = (const float*)d_in[2];
    const int*   member_idx = (const int*)d_in[3];
    const int*   rui_rows = (const int*)d_in[4];
    const int*   rui_cols = (const int*)d_in[5];
    const float* rui_vals = (const float*)d_in[6];
    const int*   rgu_rows = (const int*)d_in[7];
    const int*   rgu_cols = (const int*)d_in[8];
    const float* rgu_vals = (const float*)d_in[9];
    const int*   rgi_rows = (const int*)d_in[10];
    const int*   rgi_cols = (const int*)d_in[11];
    const float* rgi_vals = (const float*)d_in[12];
    const float* Wu = (const float*)d_in[13];
    const float* bu = (const float*)d_in[14];
    const float* Wi = (const float*)d_in[15];
    const float* bi = (const float*)d_in[16];
    const float* Wg = (const float*)d_in[17];
    const float* bg = (const float*)d_in[18];

    float* out = (float*)d_out;
    float* out_g = out;
    float* out_u = out + (size_t)GN * FN;
    float* out_i = out + (size_t)(GN + UN) * FN;

    void *p_rui_ei, *p_rgu_t, *p_rgi_t, *p_rui_t, *p_rgi_ei, *p_rgu_eu,
         *p_att_g, *p_attitem, *p_sum;
    cudaGetSymbolAddress(&p_rui_ei, g_rui_ei);
    cudaGetSymbolAddress(&p_rgu_t, g_rgu_t);
    cudaGetSymbolAddress(&p_rgi_t, g_rgi_t);
    cudaGetSymbolAddress(&p_rui_t, g_rui_t);
    cudaGetSymbolAddress(&p_rgi_ei, g_rgi_ei);
    cudaGetSymbolAddress(&p_rgu_eu, g_rgu_eu);
    cudaGetSymbolAddress(&p_att_g, g_att_g);
    cudaGetSymbolAddress(&p_attitem, g_attitem);
    cudaGetSymbolAddress(&p_sum, g_sum);

    cudaMemsetAsync(p_rui_ei, 0, sizeof(float) * (size_t)UN * FN);
    cudaMemsetAsync(p_rgu_t, 0, sizeof(float) * (size_t)UN * FN);
    cudaMemsetAsync(p_rgi_t, 0, sizeof(float) * (size_t)IN_ * FN);
    cudaMemsetAsync(p_rui_t, 0, sizeof(float) * (size_t)IN_ * FN);
    cudaMemsetAsync(p_rgi_ei, 0, sizeof(float) * (size_t)GN * FN);
    cudaMemsetAsync(p_rgu_eu, 0, sizeof(float) * (size_t)GN * FN);
    cudaMemsetAsync(p_att_g, 0, sizeof(float) * (size_t)GN * FN);
    cudaMemsetAsync(p_sum, 0, sizeof(float) * MN);

    fat0_k<<<1144, 256>>>(user_emb, member_idx, item_emb, Wu, Wi, Wg);
    fat1_k<<<92620, 256, 22528>>>(rui_rows, rui_cols, rui_vals,
                                  rgu_rows, rgu_cols, rgu_vals,
                                  rgi_rows, rgi_cols, rgi_vals,
                                  item_emb, user_emb, group_emb);
    inv_bmat_k<<<512, 256>>>();
    fat2_k<<<1358, 256, 47616>>>(user_emb, item_emb, bu, bi, out_u, out_i);
    attn2_reduce_k<<<(IN_ * FN / 4 + 255) / 256, 256>>>(item_emb);
    spmm_k<<<(NNZ_RGI + 7) / 8, 256>>>(rgi_rows, rgi_cols, rgi_vals,
                                       (const float*)p_attitem,
                                       (float*)p_att_g, NNZ_RGI);
    lin5_group_k<<<GN / 128, 256, 47616>>>(group_emb, bg, out_g);
}

// round 10
// speedup vs baseline: 1.5505x; 1.5505x over previous
#include <cuda_runtime.h>
#include <cuda_fp16.h>
#include <math.h>
#include <stdint.h>

#define GN 4096
#define UN 100000
#define IN_ 8192
#define FN 128
#define MN 8192
#define NNZ_RUI 500000
#define NNZ_RGU 8192
#define NNZ_RGI 200000
#define SPLIT 8
#define MCH (MN / SPLIT)

// ---------------- stream/event objects (host-side, created once) -------------
static cudaStream_t s_b;
static cudaEvent_t s_e0, s_e1;
namespace {
struct StreamInit {
    StreamInit() {
        cudaStreamCreateWithFlags(&s_b, cudaStreamNonBlocking);
        cudaEventCreateWithFlags(&s_e0, cudaEventDisableTiming);
        cudaEventCreateWithFlags(&s_e1, cudaEventDisableTiming);
    }
};
StreamInit s_init_;
}  // namespace

// ---------------- scratch (device globals) ----------------------------------
__device__ float  g_rui_ei[(size_t)UN * FN];
__device__ float  g_rgu_t [(size_t)UN * FN];
__device__ float  g_rgi_t [(size_t)IN_ * FN];
__device__ float  g_rui_t [(size_t)IN_ * FN];
__device__ float  g_rgi_ei[(size_t)GN * FN];
__device__ float  g_rgu_eu[(size_t)GN * FN];
__device__ float  g_att_g [(size_t)GN * FN];
__device__ float  g_attitem[(size_t)IN_ * FN];
__device__ float  g_acc[(size_t)IN_ * FN];      // attn2 atomic accumulator
__device__ float  g_sum[MN];
__device__ __half g_members_h[(size_t)MN * FN];
__device__ __half g_item_h[(size_t)IN_ * FN];
__device__ __half g_bmat[(size_t)MN * FN];
__device__ __half g_S[(size_t)MN * IN_];
__device__ __half g_Wu_h[5 * FN * FN];
__device__ __half g_Wi_h[5 * FN * FN];
__device__ __half g_Wg_h[5 * FN * FN];

// ---------------- helpers ----------------------------------------------------
__device__ __forceinline__ uint32_t s2u(const void* p) {
    uint32_t a;
    asm("{ .reg .u64 t; cvta.to.shared.u64 t, %1; cvt.u32.u64 %0, t; }"
        : "=r"(a) : "l"(p));
    return a;
}
__device__ __forceinline__ void ldsm4(uint32_t* r, uint32_t addr) {
    asm volatile("ldmatrix.sync.aligned.m8n8.x4.shared.b16 {%0,%1,%2,%3}, [%4];"
                 : "=r"(r[0]), "=r"(r[1]), "=r"(r[2]), "=r"(r[3]) : "r"(addr));
}
__device__ __forceinline__ void ldsm4t(uint32_t* r, uint32_t addr) {
    asm volatile("ldmatrix.sync.aligned.m8n8.x4.trans.shared.b16 {%0,%1,%2,%3}, [%4];"
                 : "=r"(r[0]), "=r"(r[1]), "=r"(r[2]), "=r"(r[3]) : "r"(addr));
}
__device__ __forceinline__ void mma16(float* c, const uint32_t* a, const uint32_t* b) {
    asm volatile(
        "mma.sync.aligned.m16n8k16.row.col.f32.f16.f16.f32 "
        "{%0,%1,%2,%3},{%4,%5,%6,%7},{%8,%9},{%0,%1,%2,%3};"
        : "+f"(c[0]), "+f"(c[1]), "+f"(c[2]), "+f"(c[3])
        : "r"(a[0]), "r"(a[1]), "r"(a[2]), "r"(a[3]), "r"(b[0]), "r"(b[1]));
}
__device__ __forceinline__ void red4(float* o, float x, float y, float z, float w) {
    asm volatile("red.global.add.v4.f32 [%0], {%1,%2,%3,%4};"
                 :: "l"(o), "f"(x), "f"(y), "f"(z), "f"(w) : "memory");
}
__device__ __forceinline__ void red2(float* o, float x, float y) {
    asm volatile("red.global.add.v2.f32 [%0], {%1,%2};"
                 :: "l"(o), "f"(x), "f"(y) : "memory");
}
__device__ __forceinline__ float pexp(float x) {
    float r = 2.7557319e-6f;
    r = fmaf(r, x, 2.4801587e-5f);
    r = fmaf(r, x, 1.9841270e-4f);
    r = fmaf(r, x, 1.3888889e-3f);
    r = fmaf(r, x, 8.3333333e-3f);
    r = fmaf(r, x, 4.1666667e-2f);
    r = fmaf(r, x, 1.6666667e-1f);
    r = fmaf(r, x, 0.5f);
    r = fmaf(r, x, 1.0f);
    r = fmaf(r, x, 1.0f);
    return r;
}
__device__ __forceinline__ uint32_t h2u(__half2 h) { return *(uint32_t*)&h; }
__device__ __forceinline__ uint4 f8_to_h8(float4 v0, float4 v1) {
    uint4 o;
    o.x = h2u(__floats2half2_rn(v0.x, v0.y));
    o.y = h2u(__floats2half2_rn(v0.z, v0.w));
    o.z = h2u(__floats2half2_rn(v1.x, v1.y));
    o.w = h2u(__floats2half2_rn(v1.z, v1.w));
    return o;
}
__device__ __forceinline__ uint4 hmul8(uint4 a, uint4 b) {
    uint4 o;
    o.x = h2u(__hmul2(*(__half2*)&a.x, *(__half2*)&b.x));
    o.y = h2u(__hmul2(*(__half2*)&a.y, *(__half2*)&b.y));
    o.z = h2u(__hmul2(*(__half2*)&a.z, *(__half2*)&b.z));
    o.w = h2u(__hmul2(*(__half2*)&a.w, *(__half2*)&b.w));
    return o;
}

// =============== fat0: all fp32->fp16 conversions + member gather =============
__global__ __launch_bounds__(256) void fat0_k(
    const float* __restrict__ user, const int* __restrict__ idx,
    const float* __restrict__ item,
    const float* __restrict__ Wu, const float* __restrict__ Wi,
    const float* __restrict__ Wg) {
    int bid = blockIdx.x;
    int t = (bid & 511) * 256 + threadIdx.x;
    if (bid < 512) {                          // gather members
        int m = t >> 4, j = t & 15;
        const float* src = user + (size_t)idx[m] * FN + j * 8;
        ((uint4*)g_members_h)[t] =
            f8_to_h8(*(const float4*)src, *(const float4*)(src + 4));
    } else if (bid < 1024) {                  // item conv
        float4 v0 = ((const float4*)item)[t * 2];
        float4 v1 = ((const float4*)item)[t * 2 + 1];
        ((uint4*)g_item_h)[t] = f8_to_h8(v0, v1);
    } else {                                  // W convs: 40 CTAs each
        int g = (bid - 1024) / 40, lb = (bid - 1024) % 40;
        int u = lb * 256 + threadIdx.x;
        if (u < 10240) {
            const float* src = g == 0 ? Wu : (g == 1 ? Wi : Wg);
            __half* dst = g == 0 ? g_Wu_h : (g == 1 ? g_Wi_h : g_Wg_h);
            float4 v0 = ((const float4*)src)[u * 2];
            float4 v1 = ((const float4*)src)[u * 2 + 1];
            ((uint4*)dst)[u] = f8_to_h8(v0, v1);
        }
    }
}

// =============== GEMM1 (fp16 mma) + exp + row-sum ==============================
#define PIT 40
__global__ __launch_bounds__(256) void gemm_s_k() {
    __shared__ __half As[128 * PIT];
    __shared__ __half Bs[128 * PIT];
    __shared__ float rs[128][4];
    int bm = blockIdx.y * 128, bn = blockIdx.x * 128;
    int tid = threadIdx.x, lane = tid & 31, warp = tid >> 5;
    int wm = warp >> 2, wn = warp & 3;
    int qr = lane >> 2, qc = lane & 3;
    int q = lane >> 3, r = lane & 7;
    uint32_t abase = s2u(As), bbase = s2u(Bs);
    float acc[4][4][4];
#pragma unroll
    for (int i = 0; i < 4; i++)
#pragma unroll
        for (int j = 0; j < 4; j++)
#pragma unroll
            for (int c = 0; c < 4; c++) acc[i][j][c] = 0.f;

#pragma unroll
    for (int k0 = 0; k0 < FN; k0 += 32) {
#pragma unroll
        for (int it = 0; it < 2; ++it) {
            int ch = tid + it * 256;
            int row = ch >> 2, c8 = (ch & 3) * 8;
            *(uint4*)&As[row * PIT + c8] =
                *(const uint4*)(g_members_h + (size_t)(bm + row) * FN + k0 + c8);
            *(uint4*)&Bs[row * PIT + c8] =
                *(const uint4*)(g_item_h + (size_t)(bn + row) * FN + k0 + c8);
        }
        __syncthreads();
#pragma unroll
        for (int ks = 0; ks < 2; ++ks) {
            int kl = ks * 16 + (q >> 1) * 8;
            uint32_t a[4][4], b[4][2];
#pragma unroll
            for (int mi = 0; mi < 4; ++mi) {
                int arow = wm * 64 + mi * 16 + (q & 1) * 8 + r;
                ldsm4(a[mi], abase + (arow * PIT + kl) * 2);
            }
#pragma unroll
            for (int j = 0; j < 2; ++j) {
                int brow = wn * 32 + j * 16 + (q & 1) * 8 + r;
                uint32_t t[4];
                ldsm4(t, bbase + (brow * PIT + kl) * 2);
                b[j * 2][0] = t[0]; b[j * 2 + 1][0] = t[1];
                b[j * 2][1] = t[2]; b[j * 2 + 1][1] = t[3];
            }
#pragma unroll
            for (int mi = 0; mi < 4; ++mi)
#pragma unroll
                for (int ni = 0; ni < 4; ++ni) mma16(acc[mi][ni], a[mi], b[ni]);
        }
        __syncthreads();
    }
#pragma unroll
    for (int mi = 0; mi < 4; ++mi) {
        int r0 = wm * 64 + mi * 16 + qr;
        float s0 = 0.f, s1 = 0.f;
#pragma unroll
        for (int ni = 0; ni < 4; ++ni) {
            int col = bn + wn * 32 + ni * 8 + qc * 2;
            float e0 = pexp(acc[mi][ni][0]), e1 = pexp(acc[mi][ni][1]);
            float e2 = pexp(acc[mi][ni][2]), e3 = pexp(acc[mi][ni][3]);
            *(__half2*)(g_S + (size_t)(bm + r0) * IN_ + col) = __floats2half2_rn(e0, e1);
            *(__half2*)(g_S + (size_t)(bm + r0 + 8) * IN_ + col) = __floats2half2_rn(e2, e3);
            s0 += e0 + e1; s1 += e2 + e3;
        }
        s0 += __shfl_xor_sync(0xffffffffu, s0, 1);
        s0 += __shfl_xor_sync(0xffffffffu, s0, 2);
        s1 += __shfl_xor_sync(0xffffffffu, s1, 1);
        s1 += __shfl_xor_sync(0xffffffffu, s1, 2);
        if (qc == 0) { rs[r0][wn] = s0; rs[r0 + 8][wn] = s1; }
    }
    __syncthreads();
    if (tid < 128) {
        float s = rs[tid][0] + rs[tid][1] + rs[tid][2] + rs[tid][3];
        atomicAdd(&g_sum[bm + tid], s);
    }
}

__global__ void inv_bmat_k() {
    int t = blockIdx.x * blockDim.x + threadIdx.x;
    if (t >= MN * 16) return;
    int m = t >> 4;
    float sc = 4096.0f / g_sum[m];
    uint4 v = ((const uint4*)g_members_h)[t];
    __half2 s2 = __float2half2_rn(sc);
    uint4 o;
    o.x = h2u(__hmul2(*(__half2*)&v.x, s2));
    o.y = h2u(__hmul2(*(__half2*)&v.y, s2));
    o.z = h2u(__hmul2(*(__half2*)&v.z, s2));
    o.w = h2u(__hmul2(*(__half2*)&v.w, s2));
    ((uint4*)g_bmat)[t] = o;
}

// =============== GEMM2 (fp16 mma, split-K, red2 accumulation) =================
#define PIT2 136
__global__ __launch_bounds__(256) void attn2_k() {
    __shared__ __half Ssm[32 * PIT2];
    __shared__ __half Bsm[32 * PIT2];
    int bi = blockIdx.x * 128;
    int ms = blockIdx.y * MCH;
    int tid = threadIdx.x, lane = tid & 31, warp = tid >> 5;
    int wm = warp >> 2, wn = warp & 3;
    int qr = lane >> 2, qc = lane & 3;
    int q = lane >> 3, r = lane & 7;
    uint32_t sbase = s2u(Ssm), bbase = s2u(Bsm);
    float acc[4][4][4];
#pragma unroll
    for (int i = 0; i < 4; i++)
#pragma unroll
        for (int j = 0; j < 4; j++)
#pragma unroll
            for (int c = 0; c < 4; c++) acc[i][j][c] = 0.f;

    for (int m0 = ms; m0 < ms + MCH; m0 += 32) {
#pragma unroll
        for (int it = 0; it < 2; ++it) {
            int ch = tid + it * 256;
            int mm = ch >> 4, c8 = (ch & 15) * 8;
            *(uint4*)&Ssm[mm * PIT2 + c8] =
                *(const uint4*)(g_S + (size_t)(m0 + mm) * IN_ + bi + c8);
            *(uint4*)&Bsm[mm * PIT2 + c8] =
                *(const uint4*)(g_bmat + (size_t)(m0 + mm) * FN + c8);
        }
        __syncthreads();
#pragma unroll
        for (int ks = 0; ks < 2; ++ks) {
            int k0l = ks * 16;
            uint32_t a[4][4], b[4][2];
#pragma unroll
            for (int mi = 0; mi < 4; ++mi) {
                int row = k0l + (q >> 1) * 8 + r;
                int col = wm * 64 + mi * 16 + (q & 1) * 8;
                ldsm4t(a[mi], sbase + (row * PIT2 + col) * 2);
            }
#pragma unroll
            for (int j = 0; j < 2; ++j) {
                int row = k0l + (q & 1) * 8 + r;
                int col = wn * 32 + j * 16 + (q >> 1) * 8;
                uint32_t t[4];
                ldsm4t(t, bbase + (row * PIT2 + col) * 2);
                b[j * 2][0] = t[0]; b[j * 2][1] = t[1];
                b[j * 2 + 1][0] = t[2]; b[j * 2 + 1][1] = t[3];
            }
#pragma unroll
            for (int mi = 0; mi < 4; ++mi)
#pragma unroll
                for (int ni = 0; ni < 4; ++ni) mma16(acc[mi][ni], a[mi], b[ni]);
        }
        __syncthreads();
    }
    // accumulate split-K partials directly (no g_part round trip)
#pragma unroll
    for (int mi = 0; mi < 4; ++mi) {
        int r0 = wm * 64 + mi * 16 + qr;
#pragma unroll
        for (int ni = 0; ni < 4; ++ni) {
            int col = wn * 32 + ni * 8 + qc * 2;
            red2(g_acc + (size_t)(bi + r0) * FN + col, acc[mi][ni][0], acc[mi][ni][1]);
            red2(g_acc + (size_t)(bi + r0 + 8) * FN + col, acc[mi][ni][2], acc[mi][ni][3]);
        }
    }
}

// =============== attitem = g_acc * item * 2^-12 ================================
__global__ void attn2_reduce_k(const float* __restrict__ item) {
    int t = blockIdx.x * blockDim.x + threadIdx.x;
    if (t >= IN_ * FN / 4) return;
    float4 s = ((const float4*)g_acc)[t];
    float4 e = ((const float4*)item)[t];
    const float c = 0.000244140625f;  // 2^-12
    s.x *= e.x * c; s.y *= e.y * c; s.z *= e.z * c; s.w *= e.w * c;
    ((float4*)g_attitem)[t] = s;
}

// =============== dual COO scatter: out1[r]+=v*X1[c]; out2[c]+=v*X2[r] ==========
__global__ void spmm_dual_k(const int* __restrict__ rows,
                            const int* __restrict__ cols,
                            const float* __restrict__ vals,
                            const float* __restrict__ X1, float* __restrict__ out1,
                            const float* __restrict__ X2, float* __restrict__ out2,
                            int nnz) {
    int w = (int)((blockIdx.x * 256u + threadIdx.x) >> 5);
    if (w >= nnz) return;
    int lane = threadIdx.x & 31;
    int r = rows[w], c = cols[w];
    float v = vals[w];
    float4 x1 = ((const float4*)(X1 + (size_t)c * FN))[lane];
    float4 x2 = ((const float4*)(X2 + (size_t)r * FN))[lane];
    red4(out1 + (size_t)r * FN + lane * 4, v * x1.x, v * x1.y, v * x1.z, v * x1.w);
    red4(out2 + (size_t)c * FN + lane * 4, v * x2.x, v * x2.y, v * x2.z, v * x2.w);
}

// =============== single COO scatter (att_g) ====================================
__global__ void spmm_k(const int* __restrict__ rows, const int* __restrict__ cols,
                       const float* __restrict__ vals, const float* __restrict__ X,
                       float* __restrict__ out, int nnz) {
    int w = (int)((blockIdx.x * 256u + threadIdx.x) >> 5);
    if (w >= nnz) return;
    int lane = threadIdx.x & 31;
    int r = rows[w], c = cols[w];
    float v = vals[w];
    float4 x = ((const float4*)(X + (size_t)c * FN))[lane];
    float* o = out + (size_t)r * FN + lane * 4;
    red4(o, v * x.x, v * x.y, v * x.z, v * x.w);
}

// =============== fused lin5 (fp16 mma) + bias + LeakyReLU + L2 norm ===========
// MODE 0 (user/item): xs = [e, a, a*e, b*e, b];  MODE 1 (group): [e, a, b*e, a*e, c]
template <int MODE>
__global__ __launch_bounds__(256) void lin5_k(
    const float* __restrict__ E, const float* __restrict__ A,
    const float* __restrict__ B, const float* __restrict__ C4,
    const __half* __restrict__ Wh, const float* __restrict__ bias,
    float* __restrict__ out, int Md) {
    __shared__ __half raw[3][128 * 32];
    __shared__ __half As[128 * PIT];
    __shared__ __half Bs[128 * PIT];
    __shared__ float rs[128][4];
    __shared__ float bsum[128];
    int tid = threadIdx.x, lane = tid & 31, warp = tid >> 5;
    int wm = warp >> 2, wn = warp & 3;
    int qr = lane >> 2, qc = lane & 3;
    int q = lane >> 3, r = lane & 7;
    uint32_t abase = s2u(As), bbase = s2u(Bs);
    int bm = blockIdx.x * 128;
    if (tid < 128)
        bsum[tid] = bias[tid] + bias[128 + tid] + bias[256 + tid] +
                    bias[384 + tid] + bias[512 + tid];
    float acc[4][4][4];
#pragma unroll
    for (int i = 0; i < 4; i++)
#pragma unroll
        for (int j = 0; j < 4; j++)
#pragma unroll
            for (int c = 0; c < 4; c++) acc[i][j][c] = 0.f;

    for (int fbi = 0; fbi < 4; ++fbi) {
        int fb = fbi * 32;
#pragma unroll
        for (int it = 0; it < 6; ++it) {
            int ch = tid + it * 256;
            int tilei = ch / 512, rem = ch & 511;
            int row = rem >> 2, c8 = (rem & 3) * 8;
            int m = bm + row;
            float4 v0 = {0.f, 0.f, 0.f, 0.f}, v1 = {0.f, 0.f, 0.f, 0.f};
            if (m < Md) {
                const float* src = tilei == 0 ? E : (tilei == 1 ? A : B);
                size_t off = (size_t)m * FN + fb + c8;
                v0 = *(const float4*)(src + off);
                v1 = *(const float4*)(src + off + 4);
            }
            *(uint4*)&raw[tilei][row * 32 + c8] = f8_to_h8(v0, v1);
        }
        __syncthreads();
        for (int kblk = 0; kblk < 5; ++kblk) {
#pragma unroll
            for (int it = 0; it < 2; ++it) {
                int ch = tid + it * 256;
                int row = ch >> 2, c8 = (ch & 3) * 8;
                uint4 o;
                if (kblk == 0) o = *(const uint4*)&raw[0][row * 32 + c8];
                else if (kblk == 1) o = *(const uint4*)&raw[1][row * 32 + c8];
                else if (kblk == 2)
                    o = hmul8(*(const uint4*)&raw[MODE == 0 ? 1 : 2][row * 32 + c8],
                              *(const uint4*)&raw[0][row * 32 + c8]);
                else if (kblk == 3)
                    o = hmul8(*(const uint4*)&raw[MODE == 0 ? 2 : 1][row * 32 + c8],
                              *(const uint4*)&raw[0][row * 32 + c8]);
                else {
                    if (MODE == 0) o = *(const uint4*)&raw[2][row * 32 + c8];
                    else {
                        int m = bm + row;
                        float4 v0 = {0.f, 0.f, 0.f, 0.f}, v1 = v0;
                        if (m < Md) {
                            size_t off = (size_t)m * FN + fb + c8;
                            v0 = *(const float4*)(C4 + off);
                            v1 = *(const float4*)(C4 + off + 4);
                        }
                        o = f8_to_h8(v0, v1);
                    }
                }
                *(uint4*)&As[row * PIT + c8] = o;
                *(uint4*)&Bs[row * PIT + c8] =
                    *(const uint4*)(Wh + (size_t)kblk * 16384 + (size_t)row * FN + fb + c8);
            }
            __syncthreads();
#pragma unroll
            for (int ks = 0; ks < 2; ++ks) {
                int kl = ks * 16 + (q >> 1) * 8;
                uint32_t a[4][4], b[4][2];
#pragma unroll
                for (int mi = 0; mi < 4; ++mi) {
                    int arow = wm * 64 + mi * 16 + (q & 1) * 8 + r;
                    ldsm4(a[mi], abase + (arow * PIT + kl) * 2);
                }
#pragma unroll
                for (int j = 0; j < 2; ++j) {
                    int brow = wn * 32 + j * 16 + (q & 1) * 8 + r;
                    uint32_t t[4];
                    ldsm4(t, bbase + (brow * PIT + kl) * 2);
                    b[j * 2][0] = t[0]; b[j * 2 + 1][0] = t[1];
                    b[j * 2][1] = t[2]; b[j * 2 + 1][1] = t[3];
                }
#pragma unroll
                for (int mi = 0; mi < 4; ++mi)
#pragma unroll
                    for (int ni = 0; ni < 4; ++ni) mma16(acc[mi][ni], a[mi], b[ni]);
            }
            __syncthreads();
        }
    }
#pragma unroll
    for (int mi = 0; mi < 4; ++mi) {
        int r0 = wm * 64 + mi * 16 + qr;
        float s0 = 0.f, s1 = 0.f;
#pragma unroll
        for (int ni = 0; ni < 4; ++ni) {
            int col = wn * 32 + ni * 8 + qc * 2;
            float b0 = bsum[col], b1 = bsum[col + 1];
            float v0 = acc[mi][ni][0] + b0, v1 = acc[mi][ni][1] + b1;
            float v2 = acc[mi][ni][2] + b0, v3 = acc[mi][ni][3] + b1;
            v0 = v0 >= 0.f ? v0 : 0.01f * v0;
            v1 = v1 >= 0.f ? v1 : 0.01f * v1;
            v2 = v2 >= 0.f ? v2 : 0.01f * v2;
            v3 = v3 >= 0.f ? v3 : 0.01f * v3;
            acc[mi][ni][0] = v0; acc[mi][ni][1] = v1;
            acc[mi][ni][2] = v2; acc[mi][ni][3] = v3;
            s0 += v0 * v0 + v1 * v1;
            s1 += v2 * v2 + v3 * v3;
        }
        s0 += __shfl_xor_sync(0xffffffffu, s0, 1);
        s0 += __shfl_xor_sync(0xffffffffu, s0, 2);
        s1 += __shfl_xor_sync(0xffffffffu, s1, 1);
        s1 += __shfl_xor_sync(0xffffffffu, s1, 2);
        if (qc == 0) { rs[r0][wn] = s0; rs[r0 + 8][wn] = s1; }
    }
    __syncthreads();
#pragma unroll
    for (int mi = 0; mi < 4; ++mi) {
        int r0 = wm * 64 + mi * 16 + qr;
        float t0 = rs[r0][0] + rs[r0][1] + rs[r0][2] + rs[r0][3];
        float t1 = rs[r0 + 8][0] + rs[r0 + 8][1] + rs[r0 + 8][2] + rs[r0 + 8][3];
        float i0 = 1.0f / fmaxf(sqrtf(t0), 1e-12f);
        float i1 = 1.0f / fmaxf(sqrtf(t1), 1e-12f);
        int m0g = bm + r0, m1g = m0g + 8;
#pragma unroll
        for (int ni = 0; ni < 4; ++ni) {
            int col = wn * 32 + ni * 8 + qc * 2;
            if (m0g < Md) {
                float2 v = {acc[mi][ni][0] * i0, acc[mi][ni][1] * i0};
                *(float2*)(out + (size_t)m0g * FN + col) = v;
            }
            if (m1g < Md) {
                float2 v = {acc[mi][ni][2] * i1, acc[mi][ni][3] * i1};
                *(float2*)(out + (size_t)m1g * FN + col) = v;
            }
        }
    }
}

// =============== launch =========================================================
extern "C" void kernel_launch(void* const* d_in, const int* in_sizes, int n_in,
                              void* d_out, int out_size) {
    const float* group_emb = (const float*)d_in[0];
    const float* user_emb  = (const float*)d_in[1];
    const float* item_emb  = (const float*)d_in[2];
    const int*   member_idx = (const int*)d_in[3];
    const int*   rui_rows = (const int*)d_in[4];
    const int*   rui_cols = (const int*)d_in[5];
    const float* rui_vals = (const float*)d_in[6];
    const int*   rgu_rows = (const int*)d_in[7];
    const int*   rgu_cols = (const int*)d_in[8];
    const float* rgu_vals = (const float*)d_in[9];
    const int*   rgi_rows = (const int*)d_in[10];
    const int*   rgi_cols = (const int*)d_in[11];
    const float* rgi_vals = (const float*)d_in[12];
    const float* Wu = (const float*)d_in[13];
    const float* bu = (const float*)d_in[14];
    const float* Wi = (const float*)d_in[15];
    const float* bi = (const float*)d_in[16];
    const float* Wg = (const float*)d_in[17];
    const float* bg = (const float*)d_in[18];

    float* out = (float*)d_out;
    float* out_g = out;
    float* out_u = out + (size_t)GN * FN;
    float* out_i = out + (size_t)(GN + UN) * FN;

    void *p_rui_ei, *p_rgu_t, *p_rgi_t, *p_rui_t, *p_rgi_ei, *p_rgu_eu,
         *p_att_g, *p_attitem, *p_sum, *p_acc, *p_wu, *p_wi, *p_wg;
    cudaGetSymbolAddress(&p_rui_ei, g_rui_ei);
    cudaGetSymbolAddress(&p_rgu_t, g_rgu_t);
    cudaGetSymbolAddress(&p_rgi_t, g_rgi_t);
    cudaGetSymbolAddress(&p_rui_t, g_rui_t);
    cudaGetSymbolAddress(&p_rgi_ei, g_rgi_ei);
    cudaGetSymbolAddress(&p_rgu_eu, g_rgu_eu);
    cudaGetSymbolAddress(&p_att_g, g_att_g);
    cudaGetSymbolAddress(&p_attitem, g_attitem);
    cudaGetSymbolAddress(&p_sum, g_sum);
    cudaGetSymbolAddress(&p_acc, g_acc);
    cudaGetSymbolAddress(&p_wu, g_Wu_h);
    cudaGetSymbolAddress(&p_wi, g_Wi_h);
    cudaGetSymbolAddress(&p_wg, g_Wg_h);

    // prologue on origin stream: zero accumulators + conversions/gather
    cudaMemsetAsync(p_rui_ei, 0, sizeof(float) * (size_t)UN * FN);
    cudaMemsetAsync(p_rgu_t, 0, sizeof(float) * (size_t)UN * FN);
    cudaMemsetAsync(p_rgi_t, 0, sizeof(float) * (size_t)IN_ * FN);
    cudaMemsetAsync(p_rui_t, 0, sizeof(float) * (size_t)IN_ * FN);
    cudaMemsetAsync(p_rgi_ei, 0, sizeof(float) * (size_t)GN * FN);
    cudaMemsetAsync(p_rgu_eu, 0, sizeof(float) * (size_t)GN * FN);
    cudaMemsetAsync(p_att_g, 0, sizeof(float) * (size_t)GN * FN);
    cudaMemsetAsync(p_sum, 0, sizeof(float) * MN);
    cudaMemsetAsync(p_acc, 0, sizeof(float) * (size_t)IN_ * FN);
    fat0_k<<<1144, 256>>>(user_emb, member_idx, item_emb, Wu, Wi, Wg);

    // fork: chain B on s_b (scatters + user/item lin5)
    cudaEventRecord(s_e0, 0);
    cudaStreamWaitEvent(s_b, s_e0, 0);
    spmm_dual_k<<<(NNZ_RUI + 7) / 8, 256, 0, s_b>>>(
        rui_rows, rui_cols, rui_vals, item_emb, (float*)p_rui_ei,
        user_emb, (float*)p_rui_t, NNZ_RUI);
    spmm_dual_k<<<(NNZ_RGU + 7) / 8, 256, 0, s_b>>>(
        rgu_rows, rgu_cols, rgu_vals, user_emb, (float*)p_rgu_eu,
        group_emb, (float*)p_rgu_t, NNZ_RGU);
    spmm_dual_k<<<(NNZ_RGI + 7) / 8, 256, 0, s_b>>>(
        rgi_rows, rgi_cols, rgi_vals, item_emb, (float*)p_rgi_ei,
        group_emb, (float*)p_rgi_t, NNZ_RGI);
    lin5_k<0><<<(UN + 127) / 128, 256, 0, s_b>>>(
        user_emb, (const float*)p_rui_ei, (const float*)p_rgu_t, nullptr,
        (const __half*)p_wu, bu, out_u, UN);
    lin5_k<0><<<IN_ / 128, 256, 0, s_b>>>(
        item_emb, (const float*)p_rui_t, (const float*)p_rgi_t, nullptr,
        (const __half*)p_wi, bi, out_i, IN_);
    cudaEventRecord(s_e1, s_b);

    // chain A on origin stream: attention path
    gemm_s_k<<<dim3(IN_ / 128, MN / 128), 256>>>();
    inv_bmat_k<<<512, 256>>>();
    attn2_k<<<dim3(IN_ / 128, SPLIT), 256>>>();
    attn2_reduce_k<<<(IN_ * FN / 4 + 255) / 256, 256>>>(item_emb);
    spmm_k<<<(NNZ_RGI + 7) / 8, 256>>>(rgi_rows, rgi_cols, rgi_vals,
                                       (const float*)p_attitem,
                                       (float*)p_att_g, NNZ_RGI);

    // join: group lin5 needs chain B's rgi_ei / rgu_eu
    cudaStreamWaitEvent(0, s_e1, 0);
    lin5_k<1><<<GN / 128, 256>>>(group_emb, (const float*)p_rgi_ei,
                                 (const float*)p_rgu_eu, (const float*)p_att_g,
                                 (const __half*)p_wg, bg, out_g, GN);
}

// round 11
// speedup vs baseline: 1.6116x; 1.0394x over previous
#include <cuda_runtime.h>
#include <cuda_fp16.h>
#include <math.h>
#include <stdint.h>

#define GN 4096
#define UN 100000
#define IN_ 8192
#define FN 128
#define MN 8192
#define NNZ_RUI 500000
#define NNZ_RGU 8192
#define NNZ_RGI 200000
#define SPLIT 8
#define MCH (MN / SPLIT)

// ---------------- stream/event objects (host-side, created once) -------------
static cudaStream_t s_b;
static cudaEvent_t s_e0, s_e1, s_e2;
namespace {
struct StreamInit {
    StreamInit() {
        cudaStreamCreateWithFlags(&s_b, cudaStreamNonBlocking);
        cudaEventCreateWithFlags(&s_e0, cudaEventDisableTiming);
        cudaEventCreateWithFlags(&s_e1, cudaEventDisableTiming);
        cudaEventCreateWithFlags(&s_e2, cudaEventDisableTiming);
    }
};
StreamInit s_init_;
}  // namespace

// ---------------- scratch (device globals) ----------------------------------
__device__ float  g_rui_ei[(size_t)UN * FN];
__device__ float  g_rgu_t [(size_t)UN * FN];
__device__ float  g_rgi_t [(size_t)IN_ * FN];
__device__ float  g_rui_t [(size_t)IN_ * FN];
__device__ float  g_rgi_ei[(size_t)GN * FN];
__device__ float  g_rgu_eu[(size_t)GN * FN];
__device__ float  g_att_g [(size_t)GN * FN];
__device__ float  g_attitem[(size_t)IN_ * FN];
__device__ float  g_acc[(size_t)IN_ * FN];      // attn2 atomic accumulator
__device__ float  g_sum[MN];
__device__ __half g_members_h[(size_t)MN * FN];
__device__ __half g_item_h[(size_t)IN_ * FN];
__device__ __half g_bmat[(size_t)MN * FN];
__device__ __half g_S[(size_t)MN * IN_];
__device__ __half g_Wu_h[5 * FN * FN];
__device__ __half g_Wi_h[5 * FN * FN];
__device__ __half g_Wg_h[5 * FN * FN];

// ---------------- helpers ----------------------------------------------------
__device__ __forceinline__ uint32_t s2u(const void* p) {
    uint32_t a;
    asm("{ .reg .u64 t; cvta.to.shared.u64 t, %1; cvt.u32.u64 %0, t; }"
        : "=r"(a) : "l"(p));
    return a;
}
__device__ __forceinline__ void ldsm4(uint32_t* r, uint32_t addr) {
    asm volatile("ldmatrix.sync.aligned.m8n8.x4.shared.b16 {%0,%1,%2,%3}, [%4];"
                 : "=r"(r[0]), "=r"(r[1]), "=r"(r[2]), "=r"(r[3]) : "r"(addr));
}
__device__ __forceinline__ void ldsm4t(uint32_t* r, uint32_t addr) {
    asm volatile("ldmatrix.sync.aligned.m8n8.x4.trans.shared.b16 {%0,%1,%2,%3}, [%4];"
                 : "=r"(r[0]), "=r"(r[1]), "=r"(r[2]), "=r"(r[3]) : "r"(addr));
}
__device__ __forceinline__ void mma16(float* c, const uint32_t* a, const uint32_t* b) {
    asm volatile(
        "mma.sync.aligned.m16n8k16.row.col.f32.f16.f16.f32 "
        "{%0,%1,%2,%3},{%4,%5,%6,%7},{%8,%9},{%0,%1,%2,%3};"
        : "+f"(c[0]), "+f"(c[1]), "+f"(c[2]), "+f"(c[3])
        : "r"(a[0]), "r"(a[1]), "r"(a[2]), "r"(a[3]), "r"(b[0]), "r"(b[1]));
}
__device__ __forceinline__ void red4(float* o, float x, float y, float z, float w) {
    asm volatile("red.global.add.v4.f32 [%0], {%1,%2,%3,%4};"
                 :: "l"(o), "f"(x), "f"(y), "f"(z), "f"(w) : "memory");
}
__device__ __forceinline__ void red2(float* o, float x, float y) {
    asm volatile("red.global.add.v2.f32 [%0], {%1,%2};"
                 :: "l"(o), "f"(x), "f"(y) : "memory");
}
__device__ __forceinline__ float pexp(float x) {
    float r = 2.7557319e-6f;
    r = fmaf(r, x, 2.4801587e-5f);
    r = fmaf(r, x, 1.9841270e-4f);
    r = fmaf(r, x, 1.3888889e-3f);
    r = fmaf(r, x, 8.3333333e-3f);
    r = fmaf(r, x, 4.1666667e-2f);
    r = fmaf(r, x, 1.6666667e-1f);
    r = fmaf(r, x, 0.5f);
    r = fmaf(r, x, 1.0f);
    r = fmaf(r, x, 1.0f);
    return r;
}
__device__ __forceinline__ uint32_t h2u(__half2 h) { return *(uint32_t*)&h; }
__device__ __forceinline__ uint4 f8_to_h8(float4 v0, float4 v1) {
    uint4 o;
    o.x = h2u(__floats2half2_rn(v0.x, v0.y));
    o.y = h2u(__floats2half2_rn(v0.z, v0.w));
    o.z = h2u(__floats2half2_rn(v1.x, v1.y));
    o.w = h2u(__floats2half2_rn(v1.z, v1.w));
    return o;
}
__device__ __forceinline__ uint4 hmul8(uint4 a, uint4 b) {
    uint4 o;
    o.x = h2u(__hmul2(*(__half2*)&a.x, *(__half2*)&b.x));
    o.y = h2u(__hmul2(*(__half2*)&a.y, *(__half2*)&b.y));
    o.z = h2u(__hmul2(*(__half2*)&a.z, *(__half2*)&b.z));
    o.w = h2u(__hmul2(*(__half2*)&a.w, *(__half2*)&b.w));
    return o;
}

// =============== fat0: all fp32->fp16 conversions + member gather =============
__global__ __launch_bounds__(256) void fat0_k(
    const float* __restrict__ user, const int* __restrict__ idx,
    const float* __restrict__ item,
    const float* __restrict__ Wu, const float* __restrict__ Wi,
    const float* __restrict__ Wg) {
    int bid = blockIdx.x;
    int t = (bid & 511) * 256 + threadIdx.x;
    if (bid < 512) {                          // gather members
        int m = t >> 4, j = t & 15;
        const float* src = user + (size_t)idx[m] * FN + j * 8;
        ((uint4*)g_members_h)[t] =
            f8_to_h8(*(const float4*)src, *(const float4*)(src + 4));
    } else if (bid < 1024) {                  // item conv
        float4 v0 = ((const float4*)item)[t * 2];
        float4 v1 = ((const float4*)item)[t * 2 + 1];
        ((uint4*)g_item_h)[t] = f8_to_h8(v0, v1);
    } else {                                  // W convs: 40 CTAs each
        int g = (bid - 1024) / 40, lb = (bid - 1024) % 40;
        int u = lb * 256 + threadIdx.x;
        if (u < 10240) {
            const float* src = g == 0 ? Wu : (g == 1 ? Wi : Wg);
            __half* dst = g == 0 ? g_Wu_h : (g == 1 ? g_Wi_h : g_Wg_h);
            float4 v0 = ((const float4*)src)[u * 2];
            float4 v1 = ((const float4*)src)[u * 2 + 1];
            ((uint4*)dst)[u] = f8_to_h8(v0, v1);
        }
    }
}

// =============== GEMM1 (fp16 mma) + exp + row-sum ==============================
#define PIT 40
__global__ __launch_bounds__(256, 2) void gemm_s_k() {
    __shared__ __half As[128 * PIT];
    __shared__ __half Bs[128 * PIT];
    __shared__ float rs[128][4];
    int bm = blockIdx.y * 128, bn = blockIdx.x * 128;
    int tid = threadIdx.x, lane = tid & 31, warp = tid >> 5;
    int wm = warp >> 2, wn = warp & 3;
    int qr = lane >> 2, qc = lane & 3;
    int q = lane >> 3, r = lane & 7;
    uint32_t abase = s2u(As), bbase = s2u(Bs);
    float acc[4][4][4];
#pragma unroll
    for (int i = 0; i < 4; i++)
#pragma unroll
        for (int j = 0; j < 4; j++)
#pragma unroll
            for (int c = 0; c < 4; c++) acc[i][j][c] = 0.f;

#pragma unroll
    for (int k0 = 0; k0 < FN; k0 += 32) {
#pragma unroll
        for (int it = 0; it < 2; ++it) {
            int ch = tid + it * 256;
            int row = ch >> 2, c8 = (ch & 3) * 8;
            *(uint4*)&As[row * PIT + c8] =
                *(const uint4*)(g_members_h + (size_t)(bm + row) * FN + k0 + c8);
            *(uint4*)&Bs[row * PIT + c8] =
                *(const uint4*)(g_item_h + (size_t)(bn + row) * FN + k0 + c8);
        }
        __syncthreads();
#pragma unroll
        for (int ks = 0; ks < 2; ++ks) {
            int kl = ks * 16 + (q >> 1) * 8;
            uint32_t a[4][4], b[4][2];
#pragma unroll
            for (int mi = 0; mi < 4; ++mi) {
                int arow = wm * 64 + mi * 16 + (q & 1) * 8 + r;
                ldsm4(a[mi], abase + (arow * PIT + kl) * 2);
            }
#pragma unroll
            for (int j = 0; j < 2; ++j) {
                int brow = wn * 32 + j * 16 + (q & 1) * 8 + r;
                uint32_t t[4];
                ldsm4(t, bbase + (brow * PIT + kl) * 2);
                b[j * 2][0] = t[0]; b[j * 2 + 1][0] = t[1];
                b[j * 2][1] = t[2]; b[j * 2 + 1][1] = t[3];
            }
#pragma unroll
            for (int mi = 0; mi < 4; ++mi)
#pragma unroll
                for (int ni = 0; ni < 4; ++ni) mma16(acc[mi][ni], a[mi], b[ni]);
        }
        __syncthreads();
    }
#pragma unroll
    for (int mi = 0; mi < 4; ++mi) {
        int r0 = wm * 64 + mi * 16 + qr;
        float s0 = 0.f, s1 = 0.f;
#pragma unroll
        for (int ni = 0; ni < 4; ++ni) {
            int col = bn + wn * 32 + ni * 8 + qc * 2;
            float e0 = pexp(acc[mi][ni][0]), e1 = pexp(acc[mi][ni][1]);
            float e2 = pexp(acc[mi][ni][2]), e3 = pexp(acc[mi][ni][3]);
            *(__half2*)(g_S + (size_t)(bm + r0) * IN_ + col) = __floats2half2_rn(e0, e1);
            *(__half2*)(g_S + (size_t)(bm + r0 + 8) * IN_ + col) = __floats2half2_rn(e2, e3);
            s0 += e0 + e1; s1 += e2 + e3;
        }
        s0 += __shfl_xor_sync(0xffffffffu, s0, 1);
        s0 += __shfl_xor_sync(0xffffffffu, s0, 2);
        s1 += __shfl_xor_sync(0xffffffffu, s1, 1);
        s1 += __shfl_xor_sync(0xffffffffu, s1, 2);
        if (qc == 0) { rs[r0][wn] = s0; rs[r0 + 8][wn] = s1; }
    }
    __syncthreads();
    if (tid < 128) {
        float s = rs[tid][0] + rs[tid][1] + rs[tid][2] + rs[tid][3];
        atomicAdd(&g_sum[bm + tid], s);
    }
}

__global__ void inv_bmat_k() {
    int t = blockIdx.x * blockDim.x + threadIdx.x;
    if (t >= MN * 16) return;
    int m = t >> 4;
    float sc = 4096.0f / g_sum[m];
    uint4 v = ((const uint4*)g_members_h)[t];
    __half2 s2 = __float2half2_rn(sc);
    uint4 o;
    o.x = h2u(__hmul2(*(__half2*)&v.x, s2));
    o.y = h2u(__hmul2(*(__half2*)&v.y, s2));
    o.z = h2u(__hmul2(*(__half2*)&v.z, s2));
    o.w = h2u(__hmul2(*(__half2*)&v.w, s2));
    ((uint4*)g_bmat)[t] = o;
}

// =============== GEMM2 (fp16 mma, split-K, red2 accumulation) =================
#define PIT2 136
__global__ __launch_bounds__(256, 2) void attn2_k() {
    __shared__ __half Ssm[32 * PIT2];
    __shared__ __half Bsm[32 * PIT2];
    int bi = blockIdx.x * 128;
    int ms = blockIdx.y * MCH;
    int tid = threadIdx.x, lane = tid & 31, warp = tid >> 5;
    int wm = warp >> 2, wn = warp & 3;
    int qr = lane >> 2, qc = lane & 3;
    int q = lane >> 3, r = lane & 7;
    uint32_t sbase = s2u(Ssm), bbase = s2u(Bsm);
    float acc[4][4][4];
#pragma unroll
    for (int i = 0; i < 4; i++)
#pragma unroll
        for (int j = 0; j < 4; j++)
#pragma unroll
            for (int c = 0; c < 4; c++) acc[i][j][c] = 0.f;

    for (int m0 = ms; m0 < ms + MCH; m0 += 32) {
#pragma unroll
        for (int it = 0; it < 2; ++it) {
            int ch = tid + it * 256;
            int mm = ch >> 4, c8 = (ch & 15) * 8;
            *(uint4*)&Ssm[mm * PIT2 + c8] =
                *(const uint4*)(g_S + (size_t)(m0 + mm) * IN_ + bi + c8);
            *(uint4*)&Bsm[mm * PIT2 + c8] =
                *(const uint4*)(g_bmat + (size_t)(m0 + mm) * FN + c8);
        }
        __syncthreads();
#pragma unroll
        for (int ks = 0; ks < 2; ++ks) {
            int k0l = ks * 16;
            uint32_t a[4][4], b[4][2];
#pragma unroll
            for (int mi = 0; mi < 4; ++mi) {
                int row = k0l + (q >> 1) * 8 + r;
                int col = wm * 64 + mi * 16 + (q & 1) * 8;
                ldsm4t(a[mi], sbase + (row * PIT2 + col) * 2);
            }
#pragma unroll
            for (int j = 0; j < 2; ++j) {
                int row = k0l + (q & 1) * 8 + r;
                int col = wn * 32 + j * 16 + (q >> 1) * 8;
                uint32_t t[4];
                ldsm4t(t, bbase + (row * PIT2 + col) * 2);
                b[j * 2][0] = t[0]; b[j * 2][1] = t[1];
                b[j * 2 + 1][0] = t[2]; b[j * 2 + 1][1] = t[3];
            }
#pragma unroll
            for (int mi = 0; mi < 4; ++mi)
#pragma unroll
                for (int ni = 0; ni < 4; ++ni) mma16(acc[mi][ni], a[mi], b[ni]);
        }
        __syncthreads();
    }
    // accumulate split-K partials directly (no g_part round trip)
#pragma unroll
    for (int mi = 0; mi < 4; ++mi) {
        int r0 = wm * 64 + mi * 16 + qr;
#pragma unroll
        for (int ni = 0; ni < 4; ++ni) {
            int col = wn * 32 + ni * 8 + qc * 2;
            red2(g_acc + (size_t)(bi + r0) * FN + col, acc[mi][ni][0], acc[mi][ni][1]);
            red2(g_acc + (size_t)(bi + r0 + 8) * FN + col, acc[mi][ni][2], acc[mi][ni][3]);
        }
    }
}

// =============== attitem = g_acc * item * 2^-12 ================================
__global__ void attn2_reduce_k(const float* __restrict__ item) {
    int t = blockIdx.x * blockDim.x + threadIdx.x;
    if (t >= IN_ * FN / 4) return;
    float4 s = ((const float4*)g_acc)[t];
    float4 e = ((const float4*)item)[t];
    const float c = 0.000244140625f;  // 2^-12
    s.x *= e.x * c; s.y *= e.y * c; s.z *= e.z * c; s.w *= e.w * c;
    ((float4*)g_attitem)[t] = s;
}

// =============== dual COO scatter: out1[r]+=v*X1[c]; out2[c]+=v*X2[r] ==========
__global__ void spmm_dual_k(const int* __restrict__ rows,
                            const int* __restrict__ cols,
                            const float* __restrict__ vals,
                            const float* __restrict__ X1, float* __restrict__ out1,
                            const float* __restrict__ X2, float* __restrict__ out2,
                            int nnz) {
    int w = (int)((blockIdx.x * 256u + threadIdx.x) >> 5);
    if (w >= nnz) return;
    int lane = threadIdx.x & 31;
    int r = rows[w], c = cols[w];
    float v = vals[w];
    float4 x1 = ((const float4*)(X1 + (size_t)c * FN))[lane];
    float4 x2 = ((const float4*)(X2 + (size_t)r * FN))[lane];
    red4(out1 + (size_t)r * FN + lane * 4, v * x1.x, v * x1.y, v * x1.z, v * x1.w);
    red4(out2 + (size_t)c * FN + lane * 4, v * x2.x, v * x2.y, v * x2.z, v * x2.w);
}

// =============== single COO scatter (att_g) ====================================
__global__ void spmm_k(const int* __restrict__ rows, const int* __restrict__ cols,
                       const float* __restrict__ vals, const float* __restrict__ X,
                       float* __restrict__ out, int nnz) {
    int w = (int)((blockIdx.x * 256u + threadIdx.x) >> 5);
    if (w >= nnz) return;
    int lane = threadIdx.x & 31;
    int r = rows[w], c = cols[w];
    float v = vals[w];
    float4 x = ((const float4*)(X + (size_t)c * FN))[lane];
    float* o = out + (size_t)r * FN + lane * 4;
    red4(o, v * x.x, v * x.y, v * x.z, v * x.w);
}

// =============== fused lin5 (fp16 mma) + bias + LeakyReLU + L2 norm ===========
// MODE 0 (user/item): xs = [e, a, a*e, b*e, b];  MODE 1 (group): [e, a, b*e, a*e, c]
template <int MODE>
__global__ __launch_bounds__(256, 2) void lin5_k(
    const float* __restrict__ E, const float* __restrict__ A,
    const float* __restrict__ B, const float* __restrict__ C4,
    const __half* __restrict__ Wh, const float* __restrict__ bias,
    float* __restrict__ out, int Md) {
    __shared__ __half raw[3][128 * 32];
    __shared__ __half As[128 * PIT];
    __shared__ __half Bs[128 * PIT];
    __shared__ float rs[128][4];
    __shared__ float bsum[128];
    int tid = threadIdx.x, lane = tid & 31, warp = tid >> 5;
    int wm = warp >> 2, wn = warp & 3;
    int qr = lane >> 2, qc = lane & 3;
    int q = lane >> 3, r = lane & 7;
    uint32_t abase = s2u(As), bbase = s2u(Bs);
    int bm = blockIdx.x * 128;
    if (tid < 128)
        bsum[tid] = bias[tid] + bias[128 + tid] + bias[256 + tid] +
                    bias[384 + tid] + bias[512 + tid];
    float acc[4][4][4];
#pragma unroll
    for (int i = 0; i < 4; i++)
#pragma unroll
        for (int j = 0; j < 4; j++)
#pragma unroll
            for (int c = 0; c < 4; c++) acc[i][j][c] = 0.f;

    for (int fbi = 0; fbi < 4; ++fbi) {
        int fb = fbi * 32;
#pragma unroll
        for (int it = 0; it < 6; ++it) {
            int ch = tid + it * 256;
            int tilei = ch / 512, rem = ch & 511;
            int row = rem >> 2, c8 = (rem & 3) * 8;
            int m = bm + row;
            float4 v0 = {0.f, 0.f, 0.f, 0.f}, v1 = {0.f, 0.f, 0.f, 0.f};
            if (m < Md) {
                const float* src = tilei == 0 ? E : (tilei == 1 ? A : B);
                size_t off = (size_t)m * FN + fb + c8;
                v0 = *(const float4*)(src + off);
                v1 = *(const float4*)(src + off + 4);
            }
            *(uint4*)&raw[tilei][row * 32 + c8] = f8_to_h8(v0, v1);
        }
        __syncthreads();
        for (int kblk = 0; kblk < 5; ++kblk) {
#pragma unroll
            for (int it = 0; it < 2; ++it) {
                int ch = tid + it * 256;
                int row = ch >> 2, c8 = (ch & 3) * 8;
                uint4 o;
                if (kblk == 0) o = *(const uint4*)&raw[0][row * 32 + c8];
                else if (kblk == 1) o = *(const uint4*)&raw[1][row * 32 + c8];
                else if (kblk == 2)
                    o = hmul8(*(const uint4*)&raw[MODE == 0 ? 1 : 2][row * 32 + c8],
                              *(const uint4*)&raw[0][row * 32 + c8]);
                else if (kblk == 3)
                    o = hmul8(*(const uint4*)&raw[MODE == 0 ? 2 : 1][row * 32 + c8],
                              *(const uint4*)&raw[0][row * 32 + c8]);
                else {
                    if (MODE == 0) o = *(const uint4*)&raw[2][row * 32 + c8];
                    else {
                        int m = bm + row;
                        float4 v0 = {0.f, 0.f, 0.f, 0.f}, v1 = v0;
                        if (m < Md) {
                            size_t off = (size_t)m * FN + fb + c8;
                            v0 = *(const float4*)(C4 + off);
                            v1 = *(const float4*)(C4 + off + 4);
                        }
                        o = f8_to_h8(v0, v1);
                    }
                }
                *(uint4*)&As[row * PIT + c8] = o;
                *(uint4*)&Bs[row * PIT + c8] =
                    *(const uint4*)(Wh + (size_t)kblk * 16384 + (size_t)row * FN + fb + c8);
            }
            __syncthreads();
#pragma unroll
            for (int ks = 0; ks < 2; ++ks) {
                int kl = ks * 16 + (q >> 1) * 8;
                uint32_t a[4][4], b[4][2];
#pragma unroll
                for (int mi = 0; mi < 4; ++mi) {
                    int arow = wm * 64 + mi * 16 + (q & 1) * 8 + r;
                    ldsm4(a[mi], abase + (arow * PIT + kl) * 2);
                }
#pragma unroll
                for (int j = 0; j < 2; ++j) {
                    int brow = wn * 32 + j * 16 + (q & 1) * 8 + r;
                    uint32_t t[4];
                    ldsm4(t, bbase + (brow * PIT + kl) * 2);
                    b[j * 2][0] = t[0]; b[j * 2 + 1][0] = t[1];
                    b[j * 2][1] = t[2]; b[j * 2 + 1][1] = t[3];
                }
#pragma unroll
                for (int mi = 0; mi < 4; ++mi)
#pragma unroll
                    for (int ni = 0; ni < 4; ++ni) mma16(acc[mi][ni], a[mi], b[ni]);
            }
            __syncthreads();
        }
    }
#pragma unroll
    for (int mi = 0; mi < 4; ++mi) {
        int r0 = wm * 64 + mi * 16 + qr;
        float s0 = 0.f, s1 = 0.f;
#pragma unroll
        for (int ni = 0; ni < 4; ++ni) {
            int col = wn * 32 + ni * 8 + qc * 2;
            float b0 = bsum[col], b1 = bsum[col + 1];
            float v0 = acc[mi][ni][0] + b0, v1 = acc[mi][ni][1] + b1;
            float v2 = acc[mi][ni][2] + b0, v3 = acc[mi][ni][3] + b1;
            v0 = v0 >= 0.f ? v0 : 0.01f * v0;
            v1 = v1 >= 0.f ? v1 : 0.01f * v1;
            v2 = v2 >= 0.f ? v2 : 0.01f * v2;
            v3 = v3 >= 0.f ? v3 : 0.01f * v3;
            acc[mi][ni][0] = v0; acc[mi][ni][1] = v1;
            acc[mi][ni][2] = v2; acc[mi][ni][3] = v3;
            s0 += v0 * v0 + v1 * v1;
            s1 += v2 * v2 + v3 * v3;
        }
        s0 += __shfl_xor_sync(0xffffffffu, s0, 1);
        s0 += __shfl_xor_sync(0xffffffffu, s0, 2);
        s1 += __shfl_xor_sync(0xffffffffu, s1, 1);
        s1 += __shfl_xor_sync(0xffffffffu, s1, 2);
        if (qc == 0) { rs[r0][wn] = s0; rs[r0 + 8][wn] = s1; }
    }
    __syncthreads();
#pragma unroll
    for (int mi = 0; mi < 4; ++mi) {
        int r0 = wm * 64 + mi * 16 + qr;
        float t0 = rs[r0][0] + rs[r0][1] + rs[r0][2] + rs[r0][3];
        float t1 = rs[r0 + 8][0] + rs[r0 + 8][1] + rs[r0 + 8][2] + rs[r0 + 8][3];
        float i0 = 1.0f / fmaxf(sqrtf(t0), 1e-12f);
        float i1 = 1.0f / fmaxf(sqrtf(t1), 1e-12f);
        int m0g = bm + r0, m1g = m0g + 8;
#pragma unroll
        for (int ni = 0; ni < 4; ++ni) {
            int col = wn * 32 + ni * 8 + qc * 2;
            if (m0g < Md) {
                float2 v = {acc[mi][ni][0] * i0, acc[mi][ni][1] * i0};
                *(float2*)(out + (size_t)m0g * FN + col) = v;
            }
            if (m1g < Md) {
                float2 v = {acc[mi][ni][2] * i1, acc[mi][ni][3] * i1};
                *(float2*)(out + (size_t)m1g * FN + col) = v;
            }
        }
    }
}

// =============== launch =========================================================
extern "C" void kernel_launch(void* const* d_in, const int* in_sizes, int n_in,
                              void* d_out, int out_size) {
    const float* group_emb = (const float*)d_in[0];
    const float* user_emb  = (const float*)d_in[1];
    const float* item_emb  = (const float*)d_in[2];
    const int*   member_idx = (const int*)d_in[3];
    const int*   rui_rows = (const int*)d_in[4];
    const int*   rui_cols = (const int*)d_in[5];
    const float* rui_vals = (const float*)d_in[6];
    const int*   rgu_rows = (const int*)d_in[7];
    const int*   rgu_cols = (const int*)d_in[8];
    const float* rgu_vals = (const float*)d_in[9];
    const int*   rgi_rows = (const int*)d_in[10];
    const int*   rgi_cols = (const int*)d_in[11];
    const float* rgi_vals = (const float*)d_in[12];
    const float* Wu = (const float*)d_in[13];
    const float* bu = (const float*)d_in[14];
    const float* Wi = (const float*)d_in[15];
    const float* bi = (const float*)d_in[16];
    const float* Wg = (const float*)d_in[17];
    const float* bg = (const float*)d_in[18];

    float* out = (float*)d_out;
    float* out_g = out;
    float* out_u = out + (size_t)GN * FN;
    float* out_i = out + (size_t)(GN + UN) * FN;

    void *p_rui_ei, *p_rgu_t, *p_rgi_t, *p_rui_t, *p_rgi_ei, *p_rgu_eu,
         *p_att_g, *p_attitem, *p_sum, *p_acc, *p_wu, *p_wi, *p_wg;
    cudaGetSymbolAddress(&p_rui_ei, g_rui_ei);
    cudaGetSymbolAddress(&p_rgu_t, g_rgu_t);
    cudaGetSymbolAddress(&p_rgi_t, g_rgi_t);
    cudaGetSymbolAddress(&p_rui_t, g_rui_t);
    cudaGetSymbolAddress(&p_rgi_ei, g_rgi_ei);
    cudaGetSymbolAddress(&p_rgu_eu, g_rgu_eu);
    cudaGetSymbolAddress(&p_att_g, g_att_g);
    cudaGetSymbolAddress(&p_attitem, g_attitem);
    cudaGetSymbolAddress(&p_sum, g_sum);
    cudaGetSymbolAddress(&p_acc, g_acc);
    cudaGetSymbolAddress(&p_wu, g_Wu_h);
    cudaGetSymbolAddress(&p_wi, g_Wi_h);
    cudaGetSymbolAddress(&p_wg, g_Wg_h);

    // fork at entry: chain B owns its own memsets + scatters (independent of fat0)
    cudaEventRecord(s_e0, 0);
    cudaStreamWaitEvent(s_b, s_e0, 0);
    cudaMemsetAsync(p_rui_ei, 0, sizeof(float) * (size_t)UN * FN, s_b);
    cudaMemsetAsync(p_rgu_t, 0, sizeof(float) * (size_t)UN * FN, s_b);
    cudaMemsetAsync(p_rgi_t, 0, sizeof(float) * (size_t)IN_ * FN, s_b);
    cudaMemsetAsync(p_rui_t, 0, sizeof(float) * (size_t)IN_ * FN, s_b);
    cudaMemsetAsync(p_rgi_ei, 0, sizeof(float) * (size_t)GN * FN, s_b);
    cudaMemsetAsync(p_rgu_eu, 0, sizeof(float) * (size_t)GN * FN, s_b);
    spmm_dual_k<<<(NNZ_RUI + 7) / 8, 256, 0, s_b>>>(
        rui_rows, rui_cols, rui_vals, item_emb, (float*)p_rui_ei,
        user_emb, (float*)p_rui_t, NNZ_RUI);
    spmm_dual_k<<<(NNZ_RGU + 7) / 8, 256, 0, s_b>>>(
        rgu_rows, rgu_cols, rgu_vals, user_emb, (float*)p_rgu_eu,
        group_emb, (float*)p_rgu_t, NNZ_RGU);
    spmm_dual_k<<<(NNZ_RGI + 7) / 8, 256, 0, s_b>>>(
        rgi_rows, rgi_cols, rgi_vals, item_emb, (float*)p_rgi_ei,
        group_emb, (float*)p_rgi_t, NNZ_RGI);

    // origin: small memsets + conversions, then attention chain
    cudaMemsetAsync(p_att_g, 0, sizeof(float) * (size_t)GN * FN);
    cudaMemsetAsync(p_sum, 0, sizeof(float) * MN);
    cudaMemsetAsync(p_acc, 0, sizeof(float) * (size_t)IN_ * FN);
    fat0_k<<<1144, 256>>>(user_emb, member_idx, item_emb, Wu, Wi, Wg);
    cudaEventRecord(s_e2, 0);  // weights + fp16 operands ready

    // chain B tail: lin5 user/item need weights (s_e2) + own scatters
    cudaStreamWaitEvent(s_b, s_e2, 0);
    lin5_k<0><<<(UN + 127) / 128, 256, 0, s_b>>>(
        user_emb, (const float*)p_rui_ei, (const float*)p_rgu_t, nullptr,
        (const __half*)p_wu, bu, out_u, UN);
    lin5_k<0><<<IN_ / 128, 256, 0, s_b>>>(
        item_emb, (const float*)p_rui_t, (const float*)p_rgi_t, nullptr,
        (const __half*)p_wi, bi, out_i, IN_);
    cudaEventRecord(s_e1, s_b);

    // chain A on origin stream: attention path
    gemm_s_k<<<dim3(IN_ / 128, MN / 128), 256>>>();
    inv_bmat_k<<<512, 256>>>();
    attn2_k<<<dim3(IN_ / 128, SPLIT), 256>>>();
    attn2_reduce_k<<<(IN_ * FN / 4 + 255) / 256, 256>>>(item_emb);
    spmm_k<<<(NNZ_RGI + 7) / 8, 256>>>(rgi_rows, rgi_cols, rgi_vals,
                                       (const float*)p_attitem,
                                       (float*)p_att_g, NNZ_RGI);

    // join: group lin5 needs chain B's rgi_ei / rgu_eu
    cudaStreamWaitEvent(0, s_e1, 0);
    lin5_k<1><<<GN / 128, 256>>>(group_emb, (const float*)p_rgi_ei,
                                 (const float*)p_rgu_eu, (const float*)p_att_g,
                                 (const __half*)p_wg, bg, out_g, GN);
}

// round 12
// speedup vs baseline: 1.6861x; 1.0462x over previous
#include <cuda_runtime.h>
#include <cuda_fp16.h>
#include <math.h>
#include <stdint.h>

#define GN 4096
#define UN 100000
#define IN_ 8192
#define FN 128
#define MN 8192
#define NNZ_RUI 500000
#define NNZ_RGU 8192
#define NNZ_RGI 200000
#define SPLIT 8
#define MCH (MN / SPLIT)

// ---------------- stream/event objects (host-side, created once) -------------
static cudaStream_t s_b;
static cudaEvent_t s_e0, s_e1, s_e2;
namespace {
struct StreamInit {
    StreamInit() {
        cudaStreamCreateWithFlags(&s_b, cudaStreamNonBlocking);
        cudaEventCreateWithFlags(&s_e0, cudaEventDisableTiming);
        cudaEventCreateWithFlags(&s_e1, cudaEventDisableTiming);
        cudaEventCreateWithFlags(&s_e2, cudaEventDisableTiming);
    }
};
StreamInit s_init_;
}  // namespace

// ---------------- scratch (device globals) ----------------------------------
__device__ float  g_rui_ei[(size_t)UN * FN];
__device__ float  g_rgu_t [(size_t)UN * FN];
__device__ float  g_rgi_t [(size_t)IN_ * FN];
__device__ float  g_rui_t [(size_t)IN_ * FN];
__device__ float  g_rgi_ei[(size_t)GN * FN];
__device__ float  g_rgu_eu[(size_t)GN * FN];
__device__ float  g_att_g [(size_t)GN * FN];
__device__ float  g_attitem[(size_t)IN_ * FN];
__device__ float  g_acc[(size_t)IN_ * FN];      // attn2 atomic accumulator
__device__ float  g_sum[MN];
__device__ __half g_members_h[(size_t)MN * FN];
__device__ __half g_item_h[(size_t)IN_ * FN];
__device__ __half g_bmat[(size_t)MN * FN];
__device__ __half g_S[(size_t)MN * IN_];
__device__ __half g_Wu_h[5 * FN * FN];
__device__ __half g_Wi_h[5 * FN * FN];
__device__ __half g_Wg_h[5 * FN * FN];

// ---------------- helpers ----------------------------------------------------
__device__ __forceinline__ uint32_t s2u(const void* p) {
    uint32_t a;
    asm("{ .reg .u64 t; cvta.to.shared.u64 t, %1; cvt.u32.u64 %0, t; }"
        : "=r"(a) : "l"(p));
    return a;
}
__device__ __forceinline__ void cpa16(uint32_t s, const void* g) {
    asm volatile("cp.async.cg.shared.global [%0], [%1], 16;"
                 :: "r"(s), "l"(g) : "memory");
}
__device__ __forceinline__ void cp_commit() {
    asm volatile("cp.async.commit_group;" ::: "memory");
}
template <int N>
__device__ __forceinline__ void cp_wait() {
    asm volatile("cp.async.wait_group %0;" :: "n"(N) : "memory");
}
__device__ __forceinline__ void ldsm4(uint32_t* r, uint32_t addr) {
    asm volatile("ldmatrix.sync.aligned.m8n8.x4.shared.b16 {%0,%1,%2,%3}, [%4];"
                 : "=r"(r[0]), "=r"(r[1]), "=r"(r[2]), "=r"(r[3]) : "r"(addr));
}
__device__ __forceinline__ void ldsm4t(uint32_t* r, uint32_t addr) {
    asm volatile("ldmatrix.sync.aligned.m8n8.x4.trans.shared.b16 {%0,%1,%2,%3}, [%4];"
                 : "=r"(r[0]), "=r"(r[1]), "=r"(r[2]), "=r"(r[3]) : "r"(addr));
}
__device__ __forceinline__ void mma16(float* c, const uint32_t* a, const uint32_t* b) {
    asm volatile(
        "mma.sync.aligned.m16n8k16.row.col.f32.f16.f16.f32 "
        "{%0,%1,%2,%3},{%4,%5,%6,%7},{%8,%9},{%0,%1,%2,%3};"
        : "+f"(c[0]), "+f"(c[1]), "+f"(c[2]), "+f"(c[3])
        : "r"(a[0]), "r"(a[1]), "r"(a[2]), "r"(a[3]), "r"(b[0]), "r"(b[1]));
}
__device__ __forceinline__ void red4(float* o, float x, float y, float z, float w) {
    asm volatile("red.global.add.v4.f32 [%0], {%1,%2,%3,%4};"
                 :: "l"(o), "f"(x), "f"(y), "f"(z), "f"(w) : "memory");
}
__device__ __forceinline__ void red2(float* o, float x, float y) {
    asm volatile("red.global.add.v2.f32 [%0], {%1,%2};"
                 :: "l"(o), "f"(x), "f"(y) : "memory");
}
__device__ __forceinline__ float pexp(float x) {
    float r = 2.7557319e-6f;
    r = fmaf(r, x, 2.4801587e-5f);
    r = fmaf(r, x, 1.9841270e-4f);
    r = fmaf(r, x, 1.3888889e-3f);
    r = fmaf(r, x, 8.3333333e-3f);
    r = fmaf(r, x, 4.1666667e-2f);
    r = fmaf(r, x, 1.6666667e-1f);
    r = fmaf(r, x, 0.5f);
    r = fmaf(r, x, 1.0f);
    r = fmaf(r, x, 1.0f);
    return r;
}
__device__ __forceinline__ uint32_t h2u(__half2 h) { return *(uint32_t*)&h; }
__device__ __forceinline__ uint4 f8_to_h8(float4 v0, float4 v1) {
    uint4 o;
    o.x = h2u(__floats2half2_rn(v0.x, v0.y));
    o.y = h2u(__floats2half2_rn(v0.z, v0.w));
    o.z = h2u(__floats2half2_rn(v1.x, v1.y));
    o.w = h2u(__floats2half2_rn(v1.z, v1.w));
    return o;
}
__device__ __forceinline__ uint4 hmul8(uint4 a, uint4 b) {
    uint4 o;
    o.x = h2u(__hmul2(*(__half2*)&a.x, *(__half2*)&b.x));
    o.y = h2u(__hmul2(*(__half2*)&a.y, *(__half2*)&b.y));
    o.z = h2u(__hmul2(*(__half2*)&a.z, *(__half2*)&b.z));
    o.w = h2u(__hmul2(*(__half2*)&a.w, *(__half2*)&b.w));
    return o;
}

// =============== fat0: all fp32->fp16 conversions + member gather =============
__global__ __launch_bounds__(256) void fat0_k(
    const float* __restrict__ user, const int* __restrict__ idx,
    const float* __restrict__ item,
    const float* __restrict__ Wu, const float* __restrict__ Wi,
    const float* __restrict__ Wg) {
    int bid = blockIdx.x;
    int t = (bid & 511) * 256 + threadIdx.x;
    if (bid < 512) {                          // gather members
        int m = t >> 4, j = t & 15;
        const float* src = user + (size_t)idx[m] * FN + j * 8;
        ((uint4*)g_members_h)[t] =
            f8_to_h8(*(const float4*)src, *(const float4*)(src + 4));
    } else if (bid < 1024) {                  // item conv
        float4 v0 = ((const float4*)item)[t * 2];
        float4 v1 = ((const float4*)item)[t * 2 + 1];
        ((uint4*)g_item_h)[t] = f8_to_h8(v0, v1);
    } else {                                  // W convs: 40 CTAs each
        int g = (bid - 1024) / 40, lb = (bid - 1024) % 40;
        int u = lb * 256 + threadIdx.x;
        if (u < 10240) {
            const float* src = g == 0 ? Wu : (g == 1 ? Wi : Wg);
            __half* dst = g == 0 ? g_Wu_h : (g == 1 ? g_Wi_h : g_Wg_h);
            float4 v0 = ((const float4*)src)[u * 2];
            float4 v1 = ((const float4*)src)[u * 2 + 1];
            ((uint4*)dst)[u] = f8_to_h8(v0, v1);
        }
    }
}

// =============== GEMM1 (fp16 mma, cp.async 2-stage) + exp + row-sum ===========
#define PIT 40
__global__ __launch_bounds__(256, 2) void gemm_s_k() {
    __shared__ __half As[2][128 * PIT];
    __shared__ __half Bs[2][128 * PIT];
    __shared__ float rs[128][4];
    int bm = blockIdx.y * 128, bn = blockIdx.x * 128;
    int tid = threadIdx.x, lane = tid & 31, warp = tid >> 5;
    int wm = warp >> 2, wn = warp & 3;
    int qr = lane >> 2, qc = lane & 3;
    int q = lane >> 3, r = lane & 7;
    uint32_t abase = s2u(As), bbase = s2u(Bs);
    // each thread's fixed load slots
    int row0 = tid >> 2, c80 = (tid & 3) * 8;
    int row1 = (tid + 256) >> 2, c81 = ((tid + 256) & 3) * 8;
    float acc[4][4][4];
#pragma unroll
    for (int i = 0; i < 4; i++)
#pragma unroll
        for (int j = 0; j < 4; j++)
#pragma unroll
            for (int c = 0; c < 4; c++) acc[i][j][c] = 0.f;

    // prefetch k0 = 0 into stage 0
    {
        cpa16(abase + (0 * 128 * PIT + row0 * PIT + c80) * 2,
              g_members_h + (size_t)(bm + row0) * FN + c80);
        cpa16(abase + (0 * 128 * PIT + row1 * PIT + c81) * 2,
              g_members_h + (size_t)(bm + row1) * FN + c81);
        cpa16(bbase + (0 * 128 * PIT + row0 * PIT + c80) * 2,
              g_item_h + (size_t)(bn + row0) * FN + c80);
        cpa16(bbase + (0 * 128 * PIT + row1 * PIT + c81) * 2,
              g_item_h + (size_t)(bn + row1) * FN + c81);
        cp_commit();
    }
#pragma unroll
    for (int ki = 0; ki < 4; ++ki) {
        if (ki < 3) {
            int k0 = (ki + 1) * 32, st = (ki + 1) & 1;
            cpa16(abase + (st * 128 * PIT + row0 * PIT + c80) * 2,
                  g_members_h + (size_t)(bm + row0) * FN + k0 + c80);
            cpa16(abase + (st * 128 * PIT + row1 * PIT + c81) * 2,
                  g_members_h + (size_t)(bm + row1) * FN + k0 + c81);
            cpa16(bbase + (st * 128 * PIT + row0 * PIT + c80) * 2,
                  g_item_h + (size_t)(bn + row0) * FN + k0 + c80);
            cpa16(bbase + (st * 128 * PIT + row1 * PIT + c81) * 2,
                  g_item_h + (size_t)(bn + row1) * FN + k0 + c81);
            cp_commit();
            cp_wait<1>();
        } else {
            cp_wait<0>();
        }
        __syncthreads();
        int st = ki & 1;
        uint32_t ab = abase + st * 128 * PIT * 2;
        uint32_t bb = bbase + st * 128 * PIT * 2;
#pragma unroll
        for (int ks = 0; ks < 2; ++ks) {
            int kl = ks * 16 + (q >> 1) * 8;
            uint32_t a[4][4], b[4][2];
#pragma unroll
            for (int mi = 0; mi < 4; ++mi) {
                int arow = wm * 64 + mi * 16 + (q & 1) * 8 + r;
                ldsm4(a[mi], ab + (arow * PIT + kl) * 2);
            }
#pragma unroll
            for (int j = 0; j < 2; ++j) {
                int brow = wn * 32 + j * 16 + (q & 1) * 8 + r;
                uint32_t t[4];
                ldsm4(t, bb + (brow * PIT + kl) * 2);
                b[j * 2][0] = t[0]; b[j * 2 + 1][0] = t[1];
                b[j * 2][1] = t[2]; b[j * 2 + 1][1] = t[3];
            }
#pragma unroll
            for (int mi = 0; mi < 4; ++mi)
#pragma unroll
                for (int ni = 0; ni < 4; ++ni) mma16(acc[mi][ni], a[mi], b[ni]);
        }
        __syncthreads();
    }
#pragma unroll
    for (int mi = 0; mi < 4; ++mi) {
        int r0 = wm * 64 + mi * 16 + qr;
        float s0 = 0.f, s1 = 0.f;
#pragma unroll
        for (int ni = 0; ni < 4; ++ni) {
            int col = bn + wn * 32 + ni * 8 + qc * 2;
            float e0 = pexp(acc[mi][ni][0]), e1 = pexp(acc[mi][ni][1]);
            float e2 = pexp(acc[mi][ni][2]), e3 = pexp(acc[mi][ni][3]);
            *(__half2*)(g_S + (size_t)(bm + r0) * IN_ + col) = __floats2half2_rn(e0, e1);
            *(__half2*)(g_S + (size_t)(bm + r0 + 8) * IN_ + col) = __floats2half2_rn(e2, e3);
            s0 += e0 + e1; s1 += e2 + e3;
        }
        s0 += __shfl_xor_sync(0xffffffffu, s0, 1);
        s0 += __shfl_xor_sync(0xffffffffu, s0, 2);
        s1 += __shfl_xor_sync(0xffffffffu, s1, 1);
        s1 += __shfl_xor_sync(0xffffffffu, s1, 2);
        if (qc == 0) { rs[r0][wn] = s0; rs[r0 + 8][wn] = s1; }
    }
    __syncthreads();
    if (tid < 128) {
        float s = rs[tid][0] + rs[tid][1] + rs[tid][2] + rs[tid][3];
        atomicAdd(&g_sum[bm + tid], s);
    }
}

__global__ void inv_bmat_k() {
    int t = blockIdx.x * blockDim.x + threadIdx.x;
    if (t >= MN * 16) return;
    int m = t >> 4;
    float sc = 4096.0f / g_sum[m];
    uint4 v = ((const uint4*)g_members_h)[t];
    __half2 s2 = __float2half2_rn(sc);
    uint4 o;
    o.x = h2u(__hmul2(*(__half2*)&v.x, s2));
    o.y = h2u(__hmul2(*(__half2*)&v.y, s2));
    o.z = h2u(__hmul2(*(__half2*)&v.z, s2));
    o.w = h2u(__hmul2(*(__half2*)&v.w, s2));
    ((uint4*)g_bmat)[t] = o;
}

// =============== GEMM2 (fp16 mma, split-K, cp.async 2-stage, red2) ============
#define PIT2 136
__global__ __launch_bounds__(256, 2) void attn2_k() {
    __shared__ __half Ssm[2][32 * PIT2];
    __shared__ __half Bsm[2][32 * PIT2];
    int bi = blockIdx.x * 128;
    int ms = blockIdx.y * MCH;
    int tid = threadIdx.x, lane = tid & 31, warp = tid >> 5;
    int wm = warp >> 2, wn = warp & 3;
    int qr = lane >> 2, qc = lane & 3;
    int q = lane >> 3, r = lane & 7;
    uint32_t sbase = s2u(Ssm), bbase = s2u(Bsm);
    // fixed load slots: Ssm needs 512 chunks (2/thread), Bsm 256 (1/thread)
    int smm0 = tid >> 4, sc80 = (tid & 15) * 8;
    int smm1 = (tid + 256) >> 4, sc81 = ((tid + 256) & 15) * 8;
    int bmm = tid >> 3, bc8 = (tid & 7) * 8;  // 32 rows x 16 chunks... (tid&7)*8<64? FN=128 => 16 chunks/row; use 2 loads
    int bmm1 = (tid + 256) >> 4, bchk1 = ((tid + 256) & 15) * 8;
    int bmm0 = tid >> 4, bchk0 = (tid & 15) * 8;
    (void)bmm; (void)bc8;
    float acc[4][4][4];
#pragma unroll
    for (int i = 0; i < 4; i++)
#pragma unroll
        for (int j = 0; j < 4; j++)
#pragma unroll
            for (int c = 0; c < 4; c++) acc[i][j][c] = 0.f;

    const int NIT = MCH / 32;  // 32 iterations
    // prefetch iteration 0 into stage 0
    {
        cpa16(sbase + (0 * 32 * PIT2 + smm0 * PIT2 + sc80) * 2,
              g_S + (size_t)(ms + smm0) * IN_ + bi + sc80);
        cpa16(sbase + (0 * 32 * PIT2 + smm1 * PIT2 + sc81) * 2,
              g_S + (size_t)(ms + smm1) * IN_ + bi + sc81);
        cpa16(bbase + (0 * 32 * PIT2 + bmm0 * PIT2 + bchk0) * 2,
              g_bmat + (size_t)(ms + bmm0) * FN + bchk0);
        cpa16(bbase + (0 * 32 * PIT2 + bmm1 * PIT2 + bchk1) * 2,
              g_bmat + (size_t)(ms + bmm1) * FN + bchk1);
        cp_commit();
    }
    for (int j = 0; j < NIT; ++j) {
        if (j + 1 < NIT) {
            int m0 = ms + (j + 1) * 32, st = (j + 1) & 1;
            cpa16(sbase + (st * 32 * PIT2 + smm0 * PIT2 + sc80) * 2,
                  g_S + (size_t)(m0 + smm0) * IN_ + bi + sc80);
            cpa16(sbase + (st * 32 * PIT2 + smm1 * PIT2 + sc81) * 2,
                  g_S + (size_t)(m0 + smm1) * IN_ + bi + sc81);
            cpa16(bbase + (st * 32 * PIT2 + bmm0 * PIT2 + bchk0) * 2,
                  g_bmat + (size_t)(m0 + bmm0) * FN + bchk0);
            cpa16(bbase + (st * 32 * PIT2 + bmm1 * PIT2 + bchk1) * 2,
                  g_bmat + (size_t)(m0 + bmm1) * FN + bchk1);
            cp_commit();
            cp_wait<1>();
        } else {
            cp_wait<0>();
        }
        __syncthreads();
        int st = j & 1;
        uint32_t sb = sbase + st * 32 * PIT2 * 2;
        uint32_t bb = bbase + st * 32 * PIT2 * 2;
#pragma unroll
        for (int ks = 0; ks < 2; ++ks) {
            int k0l = ks * 16;
            uint32_t a[4][4], b[4][2];
#pragma unroll
            for (int mi = 0; mi < 4; ++mi) {
                int row = k0l + (q >> 1) * 8 + r;
                int col = wm * 64 + mi * 16 + (q & 1) * 8;
                ldsm4t(a[mi], sb + (row * PIT2 + col) * 2);
            }
#pragma unroll
            for (int jn = 0; jn < 2; ++jn) {
                int row = k0l + (q & 1) * 8 + r;
                int col = wn * 32 + jn * 16 + (q >> 1) * 8;
                uint32_t t[4];
                ldsm4t(t, bb + (row * PIT2 + col) * 2);
                b[jn * 2][0] = t[0]; b[jn * 2][1] = t[1];
                b[jn * 2 + 1][0] = t[2]; b[jn * 2 + 1][1] = t[3];
            }
#pragma unroll
            for (int mi = 0; mi < 4; ++mi)
#pragma unroll
                for (int ni = 0; ni < 4; ++ni) mma16(acc[mi][ni], a[mi], b[ni]);
        }
        __syncthreads();
    }
    // accumulate split-K partials directly (no g_part round trip)
#pragma unroll
    for (int mi = 0; mi < 4; ++mi) {
        int r0 = wm * 64 + mi * 16 + qr;
#pragma unroll
        for (int ni = 0; ni < 4; ++ni) {
            int col = wn * 32 + ni * 8 + qc * 2;
            red2(g_acc + (size_t)(bi + r0) * FN + col, acc[mi][ni][0], acc[mi][ni][1]);
            red2(g_acc + (size_t)(bi + r0 + 8) * FN + col, acc[mi][ni][2], acc[mi][ni][3]);
        }
    }
}

// =============== attitem = g_acc * item * 2^-12 ================================
__global__ void attn2_reduce_k(const float* __restrict__ item) {
    int t = blockIdx.x * blockDim.x + threadIdx.x;
    if (t >= IN_ * FN / 4) return;
    float4 s = ((const float4*)g_acc)[t];
    float4 e = ((const float4*)item)[t];
    const float c = 0.000244140625f;  // 2^-12
    s.x *= e.x * c; s.y *= e.y * c; s.z *= e.z * c; s.w *= e.w * c;
    ((float4*)g_attitem)[t] = s;
}

// =============== dual COO scatter: out1[r]+=v*X1[c]; out2[c]+=v*X2[r] ==========
__global__ void spmm_dual_k(const int* __restrict__ rows,
                            const int* __restrict__ cols,
                            const float* __restrict__ vals,
                            const float* __restrict__ X1, float* __restrict__ out1,
                            const float* __restrict__ X2, float* __restrict__ out2,
                            int nnz) {
    int w = (int)((blockIdx.x * 256u + threadIdx.x) >> 5);
    if (w >= nnz) return;
    int lane = threadIdx.x & 31;
    int r = rows[w], c = cols[w];
    float v = vals[w];
    float4 x1 = ((const float4*)(X1 + (size_t)c * FN))[lane];
    float4 x2 = ((const float4*)(X2 + (size_t)r * FN))[lane];
    red4(out1 + (size_t)r * FN + lane * 4, v * x1.x, v * x1.y, v * x1.z, v * x1.w);
    red4(out2 + (size_t)c * FN + lane * 4, v * x2.x, v * x2.y, v * x2.z, v * x2.w);
}

// =============== single COO scatter (att_g) ====================================
__global__ void spmm_k(const int* __restrict__ rows, const int* __restrict__ cols,
                       const float* __restrict__ vals, const float* __restrict__ X,
                       float* __restrict__ out, int nnz) {
    int w = (int)((blockIdx.x * 256u + threadIdx.x) >> 5);
    if (w >= nnz) return;
    int lane = threadIdx.x & 31;
    int r = rows[w], c = cols[w];
    float v = vals[w];
    float4 x = ((const float4*)(X + (size_t)c * FN))[lane];
    float* o = out + (size_t)r * FN + lane * 4;
    red4(o, v * x.x, v * x.y, v * x.z, v * x.w);
}

// =============== fused lin5 (fp16 mma) + bias + LeakyReLU + L2 norm ===========
// MODE 0 (user/item): xs = [e, a, a*e, b*e, b];  MODE 1 (group): [e, a, b*e, a*e, c]
template <int MODE>
__global__ __launch_bounds__(256, 2) void lin5_k(
    const float* __restrict__ E, const float* __restrict__ A,
    const float* __restrict__ B, const float* __restrict__ C4,
    const __half* __restrict__ Wh, const float* __restrict__ bias,
    float* __restrict__ out, int Md) {
    __shared__ __half raw[3][128 * 32];
    __shared__ __half As[128 * PIT];
    __shared__ __half Bs[128 * PIT];
    __shared__ float rs[128][4];
    __shared__ float bsum[128];
    int tid = threadIdx.x, lane = tid & 31, warp = tid >> 5;
    int wm = warp >> 2, wn = warp & 3;
    int qr = lane >> 2, qc = lane & 3;
    int q = lane >> 3, r = lane & 7;
    uint32_t abase = s2u(As), bbase = s2u(Bs);
    int bm = blockIdx.x * 128;
    if (tid < 128)
        bsum[tid] = bias[tid] + bias[128 + tid] + bias[256 + tid] +
                    bias[384 + tid] + bias[512 + tid];
    float acc[4][4][4];
#pragma unroll
    for (int i = 0; i < 4; i++)
#pragma unroll
        for (int j = 0; j < 4; j++)
#pragma unroll
            for (int c = 0; c < 4; c++) acc[i][j][c] = 0.f;

    for (int fbi = 0; fbi < 4; ++fbi) {
        int fb = fbi * 32;
#pragma unroll
        for (int it = 0; it < 6; ++it) {
            int ch = tid + it * 256;
            int tilei = ch / 512, rem = ch & 511;
            int row = rem >> 2, c8 = (rem & 3) * 8;
            int m = bm + row;
            float4 v0 = {0.f, 0.f, 0.f, 0.f}, v1 = {0.f, 0.f, 0.f, 0.f};
            if (m < Md) {
                const float* src = tilei == 0 ? E : (tilei == 1 ? A : B);
                size_t off = (size_t)m * FN + fb + c8;
                v0 = *(const float4*)(src + off);
                v1 = *(const float4*)(src + off + 4);
            }
            *(uint4*)&raw[tilei][row * 32 + c8] = f8_to_h8(v0, v1);
        }
        __syncthreads();
        for (int kblk = 0; kblk < 5; ++kblk) {
#pragma unroll
            for (int it = 0; it < 2; ++it) {
                int ch = tid + it * 256;
                int row = ch >> 2, c8 = (ch & 3) * 8;
                uint4 o;
                if (kblk == 0) o = *(const uint4*)&raw[0][row * 32 + c8];
                else if (kblk == 1) o = *(const uint4*)&raw[1][row * 32 + c8];
                else if (kblk == 2)
                    o = hmul8(*(const uint4*)&raw[MODE == 0 ? 1 : 2][row * 32 + c8],
                              *(const uint4*)&raw[0][row * 32 + c8]);
                else if (kblk == 3)
                    o = hmul8(*(const uint4*)&raw[MODE == 0 ? 2 : 1][row * 32 + c8],
                              *(const uint4*)&raw[0][row * 32 + c8]);
                else {
                    if (MODE == 0) o = *(const uint4*)&raw[2][row * 32 + c8];
                    else {
                        int m = bm + row;
                        float4 v0 = {0.f, 0.f, 0.f, 0.f}, v1 = v0;
                        if (m < Md) {
                            size_t off = (size_t)m * FN + fb + c8;
                            v0 = *(const float4*)(C4 + off);
                            v1 = *(const float4*)(C4 + off + 4);
                        }
                        o = f8_to_h8(v0, v1);
                    }
                }
                *(uint4*)&As[row * PIT + c8] = o;
                *(uint4*)&Bs[row * PIT + c8] =
                    *(const uint4*)(Wh + (size_t)kblk * 16384 + (size_t)row * FN + fb + c8);
            }
            __syncthreads();
#pragma unroll
            for (int ks = 0; ks < 2; ++ks) {
                int kl = ks * 16 + (q >> 1) * 8;
                uint32_t a[4][4], b[4][2];
#pragma unroll
                for (int mi = 0; mi < 4; ++mi) {
                    int arow = wm * 64 + mi * 16 + (q & 1) * 8 + r;
                    ldsm4(a[mi], abase + (arow * PIT + kl) * 2);
                }
#pragma unroll
                for (int j = 0; j < 2; ++j) {
                    int brow = wn * 32 + j * 16 + (q & 1) * 8 + r;
                    uint32_t t[4];
                    ldsm4(t, bbase + (brow * PIT + kl) * 2);
                    b[j * 2][0] = t[0]; b[j * 2 + 1][0] = t[1];
                    b[j * 2][1] = t[2]; b[j * 2 + 1][1] = t[3];
                }
#pragma unroll
                for (int mi = 0; mi < 4; ++mi)
#pragma unroll
                    for (int ni = 0; ni < 4; ++ni) mma16(acc[mi][ni], a[mi], b[ni]);
            }
            __syncthreads();
        }
    }
#pragma unroll
    for (int mi = 0; mi < 4; ++mi) {
        int r0 = wm * 64 + mi * 16 + qr;
        float s0 = 0.f, s1 = 0.f;
#pragma unroll
        for (int ni = 0; ni < 4; ++ni) {
            int col = wn * 32 + ni * 8 + qc * 2;
            float b0 = bsum[col], b1 = bsum[col + 1];
            float v0 = acc[mi][ni][0] + b0, v1 = acc[mi][ni][1] + b1;
            float v2 = acc[mi][ni][2] + b0, v3 = acc[mi][ni][3] + b1;
            v0 = v0 >= 0.f ? v0 : 0.01f * v0;
            v1 = v1 >= 0.f ? v1 : 0.01f * v1;
            v2 = v2 >= 0.f ? v2 : 0.01f * v2;
            v3 = v3 >= 0.f ? v3 : 0.01f * v3;
            acc[mi][ni][0] = v0; acc[mi][ni][1] = v1;
            acc[mi][ni][2] = v2; acc[mi][ni][3] = v3;
            s0 += v0 * v0 + v1 * v1;
            s1 += v2 * v2 + v3 * v3;
        }
        s0 += __shfl_xor_sync(0xffffffffu, s0, 1);
        s0 += __shfl_xor_sync(0xffffffffu, s0, 2);
        s1 += __shfl_xor_sync(0xffffffffu, s1, 1);
        s1 += __shfl_xor_sync(0xffffffffu, s1, 2);
        if (qc == 0) { rs[r0][wn] = s0; rs[r0 + 8][wn] = s1; }
    }
    __syncthreads();
#pragma unroll
    for (int mi = 0; mi < 4; ++mi) {
        int r0 = wm * 64 + mi * 16 + qr;
        float t0 = rs[r0][0] + rs[r0][1] + rs[r0][2] + rs[r0][3];
        float t1 = rs[r0 + 8][0] + rs[r0 + 8][1] + rs[r0 + 8][2] + rs[r0 + 8][3];
        float i0 = 1.0f / fmaxf(sqrtf(t0), 1e-12f);
        float i1 = 1.0f / fmaxf(sqrtf(t1), 1e-12f);
        int m0g = bm + r0, m1g = m0g + 8;
#pragma unroll
        for (int ni = 0; ni < 4; ++ni) {
            int col = wn * 32 + ni * 8 + qc * 2;
            if (m0g < Md) {
                float2 v = {acc[mi][ni][0] * i0, acc[mi][ni][1] * i0};
                *(float2*)(out + (size_t)m0g * FN + col) = v;
            }
            if (m1g < Md) {
                float2 v = {acc[mi][ni][2] * i1, acc[mi][ni][3] * i1};
                *(float2*)(out + (size_t)m1g * FN + col) = v;
            }
        }
    }
}

// =============== launch =========================================================
extern "C" void kernel_launch(void* const* d_in, const int* in_sizes, int n_in,
                              void* d_out, int out_size) {
    const float* group_emb = (const float*)d_in[0];
    const float* user_emb  = (const float*)d_in[1];
    const float* item_emb  = (const float*)d_in[2];
    const int*   member_idx = (const int*)d_in[3];
    const int*   rui_rows = (const int*)d_in[4];
    const int*   rui_cols = (const int*)d_in[5];
    const float* rui_vals = (const float*)d_in[6];
    const int*   rgu_rows = (const int*)d_in[7];
    const int*   rgu_cols = (const int*)d_in[8];
    const float* rgu_vals = (const float*)d_in[9];
    const int*   rgi_rows = (const int*)d_in[10];
    const int*   rgi_cols = (const int*)d_in[11];
    const float* rgi_vals = (const float*)d_in[12];
    const float* Wu = (const float*)d_in[13];
    const float* bu = (const float*)d_in[14];
    const float* Wi = (const float*)d_in[15];
    const float* bi = (const float*)d_in[16];
    const float* Wg = (const float*)d_in[17];
    const float* bg = (const float*)d_in[18];

    float* out = (float*)d_out;
    float* out_g = out;
    float* out_u = out + (size_t)GN * FN;
    float* out_i = out + (size_t)(GN + UN) * FN;

    void *p_rui_ei, *p_rgu_t, *p_rgi_t, *p_rui_t, *p_rgi_ei, *p_rgu_eu,
         *p_att_g, *p_attitem, *p_sum, *p_acc, *p_wu, *p_wi, *p_wg;
    cudaGetSymbolAddress(&p_rui_ei, g_rui_ei);
    cudaGetSymbolAddress(&p_rgu_t, g_rgu_t);
    cudaGetSymbolAddress(&p_rgi_t, g_rgi_t);
    cudaGetSymbolAddress(&p_rui_t, g_rui_t);
    cudaGetSymbolAddress(&p_rgi_ei, g_rgi_ei);
    cudaGetSymbolAddress(&p_rgu_eu, g_rgu_eu);
    cudaGetSymbolAddress(&p_att_g, g_att_g);
    cudaGetSymbolAddress(&p_attitem, g_attitem);
    cudaGetSymbolAddress(&p_sum, g_sum);
    cudaGetSymbolAddress(&p_acc, g_acc);
    cudaGetSymbolAddress(&p_wu, g_Wu_h);
    cudaGetSymbolAddress(&p_wi, g_Wi_h);
    cudaGetSymbolAddress(&p_wg, g_Wg_h);

    // fork at entry: chain B owns its own memsets + scatters (independent of fat0)
    cudaEventRecord(s_e0, 0);
    cudaStreamWaitEvent(s_b, s_e0, 0);
    cudaMemsetAsync(p_rui_ei, 0, sizeof(float) * (size_t)UN * FN, s_b);
    cudaMemsetAsync(p_rgu_t, 0, sizeof(float) * (size_t)UN * FN, s_b);
    cudaMemsetAsync(p_rgi_t, 0, sizeof(float) * (size_t)IN_ * FN, s_b);
    cudaMemsetAsync(p_rui_t, 0, sizeof(float) * (size_t)IN_ * FN, s_b);
    cudaMemsetAsync(p_rgi_ei, 0, sizeof(float) * (size_t)GN * FN, s_b);
    cudaMemsetAsync(p_rgu_eu, 0, sizeof(float) * (size_t)GN * FN, s_b);
    spmm_dual_k<<<(NNZ_RUI + 7) / 8, 256, 0, s_b>>>(
        rui_rows, rui_cols, rui_vals, item_emb, (float*)p_rui_ei,
        user_emb, (float*)p_rui_t, NNZ_RUI);
    spmm_dual_k<<<(NNZ_RGU + 7) / 8, 256, 0, s_b>>>(
        rgu_rows, rgu_cols, rgu_vals, user_emb, (float*)p_rgu_eu,
        group_emb, (float*)p_rgu_t, NNZ_RGU);
    spmm_dual_k<<<(NNZ_RGI + 7) / 8, 256, 0, s_b>>>(
        rgi_rows, rgi_cols, rgi_vals, item_emb, (float*)p_rgi_ei,
        group_emb, (float*)p_rgi_t, NNZ_RGI);

    // origin: small memsets + conversions, then attention chain
    cudaMemsetAsync(p_att_g, 0, sizeof(float) * (size_t)GN * FN);
    cudaMemsetAsync(p_sum, 0, sizeof(float) * MN);
    cudaMemsetAsync(p_acc, 0, sizeof(float) * (size_t)IN_ * FN);
    fat0_k<<<1144, 256>>>(user_emb, member_idx, item_emb, Wu, Wi, Wg);
    cudaEventRecord(s_e2, 0);  // weights + fp16 operands ready

    // chain B tail: lin5 user/item need weights (s_e2) + own scatters
    cudaStreamWaitEvent(s_b, s_e2, 0);
    lin5_k<0><<<(UN + 127) / 128, 256, 0, s_b>>>(
        user_emb, (const float*)p_rui_ei, (const float*)p_rgu_t, nullptr,
        (const __half*)p_wu, bu, out_u, UN);
    lin5_k<0><<<IN_ / 128, 256, 0, s_b>>>(
        item_emb, (const float*)p_rui_t, (const float*)p_rgi_t, nullptr,
        (const __half*)p_wi, bi, out_i, IN_);
    cudaEventRecord(s_e1, s_b);

    // chain A on origin stream: attention path
    gemm_s_k<<<dim3(IN_ / 128, MN / 128), 256>>>();
    inv_bmat_k<<<512, 256>>>();
    attn2_k<<<dim3(IN_ / 128, SPLIT), 256>>>();
    attn2_reduce_k<<<(IN_ * FN / 4 + 255) / 256, 256>>>(item_emb);
    spmm_k<<<(NNZ_RGI + 7) / 8, 256>>>(rgi_rows, rgi_cols, rgi_vals,
                                       (const float*)p_attitem,
                                       (float*)p_att_g, NNZ_RGI);

    // join: group lin5 needs chain B's rgi_ei / rgu_eu
    cudaStreamWaitEvent(0, s_e1, 0);
    lin5_k<1><<<GN / 128, 256>>>(group_emb, (const float*)p_rgi_ei,
                                 (const float*)p_rgu_eu, (const float*)p_att_g,
                                 (const __half*)p_wg, bg, out_g, GN);
}

// round 13
// speedup vs baseline: 1.8427x; 1.0929x over previous
#include <cuda_runtime.h>
#include <cuda_fp16.h>
#include <math.h>
#include <stdint.h>

#define GN 4096
#define UN 100000
#define IN_ 8192
#define FN 128
#define MN 8192
#define NNZ_RUI 500000
#define NNZ_RGU 8192
#define NNZ_RGI 200000
#define SPLIT 8
#define MCH (MN / SPLIT)

// ---------------- stream/event objects (host-side, created once) -------------
static cudaStream_t s_b;
static cudaEvent_t s_e0, s_e1, s_e2;
namespace {
struct StreamInit {
    StreamInit() {
        cudaStreamCreateWithFlags(&s_b, cudaStreamNonBlocking);
        cudaEventCreateWithFlags(&s_e0, cudaEventDisableTiming);
        cudaEventCreateWithFlags(&s_e1, cudaEventDisableTiming);
        cudaEventCreateWithFlags(&s_e2, cudaEventDisableTiming);
    }
};
StreamInit s_init_;
}  // namespace

// ---------------- scratch (device globals) ----------------------------------
__device__ float  g_rui_ei[(size_t)UN * FN];
__device__ float  g_rgu_t [(size_t)UN * FN];
__device__ float  g_rgi_t [(size_t)IN_ * FN];
__device__ float  g_rui_t [(size_t)IN_ * FN];
__device__ float  g_rgi_ei[(size_t)GN * FN];
__device__ float  g_rgu_eu[(size_t)GN * FN];
__device__ float  g_att_g [(size_t)GN * FN];
__device__ float  g_attitem[(size_t)IN_ * FN];
__device__ float  g_acc[(size_t)IN_ * FN];      // attn2 atomic accumulator
__device__ float  g_sum[MN];
__device__ __half g_members_h[(size_t)MN * FN];
__device__ __half g_item_h[(size_t)IN_ * FN];
__device__ __half g_bmat[(size_t)MN * FN];
__device__ __half g_S[(size_t)MN * IN_];
__device__ __half g_Wu_h[5 * FN * FN];
__device__ __half g_Wi_h[5 * FN * FN];
__device__ __half g_Wg_h[5 * FN * FN];

// ---------------- helpers ----------------------------------------------------
__device__ __forceinline__ uint32_t s2u(const void* p) {
    uint32_t a;
    asm("{ .reg .u64 t; cvta.to.shared.u64 t, %1; cvt.u32.u64 %0, t; }"
        : "=r"(a) : "l"(p));
    return a;
}
__device__ __forceinline__ void cpa16(uint32_t s, const void* g) {
    asm volatile("cp.async.cg.shared.global [%0], [%1], 16;"
                 :: "r"(s), "l"(g) : "memory");
}
__device__ __forceinline__ void cp_commit() {
    asm volatile("cp.async.commit_group;" ::: "memory");
}
template <int N>
__device__ __forceinline__ void cp_wait() {
    asm volatile("cp.async.wait_group %0;" :: "n"(N) : "memory");
}
__device__ __forceinline__ void ldsm4(uint32_t* r, uint32_t addr) {
    asm volatile("ldmatrix.sync.aligned.m8n8.x4.shared.b16 {%0,%1,%2,%3}, [%4];"
                 : "=r"(r[0]), "=r"(r[1]), "=r"(r[2]), "=r"(r[3]) : "r"(addr));
}
__device__ __forceinline__ void ldsm4t(uint32_t* r, uint32_t addr) {
    asm volatile("ldmatrix.sync.aligned.m8n8.x4.trans.shared.b16 {%0,%1,%2,%3}, [%4];"
                 : "=r"(r[0]), "=r"(r[1]), "=r"(r[2]), "=r"(r[3]) : "r"(addr));
}
__device__ __forceinline__ void mma16(float* c, const uint32_t* a, const uint32_t* b) {
    asm volatile(
        "mma.sync.aligned.m16n8k16.row.col.f32.f16.f16.f32 "
        "{%0,%1,%2,%3},{%4,%5,%6,%7},{%8,%9},{%0,%1,%2,%3};"
        : "+f"(c[0]), "+f"(c[1]), "+f"(c[2]), "+f"(c[3])
        : "r"(a[0]), "r"(a[1]), "r"(a[2]), "r"(a[3]), "r"(b[0]), "r"(b[1]));
}
__device__ __forceinline__ void red4(float* o, float x, float y, float z, float w) {
    asm volatile("red.global.add.v4.f32 [%0], {%1,%2,%3,%4};"
                 :: "l"(o), "f"(x), "f"(y), "f"(z), "f"(w) : "memory");
}
__device__ __forceinline__ void red2(float* o, float x, float y) {
    asm volatile("red.global.add.v2.f32 [%0], {%1,%2};"
                 :: "l"(o), "f"(x), "f"(y) : "memory");
}
__device__ __forceinline__ float pexp(float x) {
    float r = 2.7557319e-6f;
    r = fmaf(r, x, 2.4801587e-5f);
    r = fmaf(r, x, 1.9841270e-4f);
    r = fmaf(r, x, 1.3888889e-3f);
    r = fmaf(r, x, 8.3333333e-3f);
    r = fmaf(r, x, 4.1666667e-2f);
    r = fmaf(r, x, 1.6666667e-1f);
    r = fmaf(r, x, 0.5f);
    r = fmaf(r, x, 1.0f);
    r = fmaf(r, x, 1.0f);
    return r;
}
__device__ __forceinline__ uint32_t h2u(__half2 h) { return *(uint32_t*)&h; }
__device__ __forceinline__ uint4 f8_to_h8(float4 v0, float4 v1) {
    uint4 o;
    o.x = h2u(__floats2half2_rn(v0.x, v0.y));
    o.y = h2u(__floats2half2_rn(v0.z, v0.w));
    o.z = h2u(__floats2half2_rn(v1.x, v1.y));
    o.w = h2u(__floats2half2_rn(v1.z, v1.w));
    return o;
}
__device__ __forceinline__ uint4 hmul8(uint4 a, uint4 b) {
    uint4 o;
    o.x = h2u(__hmul2(*(__half2*)&a.x, *(__half2*)&b.x));
    o.y = h2u(__hmul2(*(__half2*)&a.y, *(__half2*)&b.y));
    o.z = h2u(__hmul2(*(__half2*)&a.z, *(__half2*)&b.z));
    o.w = h2u(__hmul2(*(__half2*)&a.w, *(__half2*)&b.w));
    return o;
}

// =============== fat0: all fp32->fp16 conversions + member gather =============
__global__ __launch_bounds__(256) void fat0_k(
    const float* __restrict__ user, const int* __restrict__ idx,
    const float* __restrict__ item,
    const float* __restrict__ Wu, const float* __restrict__ Wi,
    const float* __restrict__ Wg) {
    int bid = blockIdx.x;
    int t = (bid & 511) * 256 + threadIdx.x;
    if (bid < 512) {                          // gather members
        int m = t >> 4, j = t & 15;
        const float* src = user + (size_t)idx[m] * FN + j * 8;
        ((uint4*)g_members_h)[t] =
            f8_to_h8(*(const float4*)src, *(const float4*)(src + 4));
    } else if (bid < 1024) {                  // item conv
        float4 v0 = ((const float4*)item)[t * 2];
        float4 v1 = ((const float4*)item)[t * 2 + 1];
        ((uint4*)g_item_h)[t] = f8_to_h8(v0, v1);
    } else {                                  // W convs: 40 CTAs each
        int g = (bid - 1024) / 40, lb = (bid - 1024) % 40;
        int u = lb * 256 + threadIdx.x;
        if (u < 10240) {
            const float* src = g == 0 ? Wu : (g == 1 ? Wi : Wg);
            __half* dst = g == 0 ? g_Wu_h : (g == 1 ? g_Wi_h : g_Wg_h);
            float4 v0 = ((const float4*)src)[u * 2];
            float4 v1 = ((const float4*)src)[u * 2 + 1];
            ((uint4*)dst)[u] = f8_to_h8(v0, v1);
        }
    }
}

// =============== GEMM1 (fp16 mma, cp.async 2-stage) + exp + staged S store ====
#define PIT 40
// SM layout (halves): A0 [0,5120) A1 [5120,10240) B0 [10240,15360) B1 [15360,20480)
// epilogue reuses SM[0,17408) as a 128x136 staging tile for coalesced S stores
__global__ __launch_bounds__(256, 2) void gemm_s_k() {
    __shared__ __half SM[20480];
    __shared__ float rs[128][4];
    int bm = blockIdx.y * 128, bn = blockIdx.x * 128;
    int tid = threadIdx.x, lane = tid & 31, warp = tid >> 5;
    int wm = warp >> 2, wn = warp & 3;
    int qr = lane >> 2, qc = lane & 3;
    int q = lane >> 3, r = lane & 7;
    uint32_t base = s2u(SM);
    int row0 = tid >> 2, c80 = (tid & 3) * 8;
    int row1 = (tid + 256) >> 2, c81 = ((tid + 256) & 3) * 8;
    float acc[4][4][4];
#pragma unroll
    for (int i = 0; i < 4; i++)
#pragma unroll
        for (int j = 0; j < 4; j++)
#pragma unroll
            for (int c = 0; c < 4; c++) acc[i][j][c] = 0.f;

    {
        cpa16(base + (row0 * PIT + c80) * 2,
              g_members_h + (size_t)(bm + row0) * FN + c80);
        cpa16(base + (row1 * PIT + c81) * 2,
              g_members_h + (size_t)(bm + row1) * FN + c81);
        cpa16(base + (10240 + row0 * PIT + c80) * 2,
              g_item_h + (size_t)(bn + row0) * FN + c80);
        cpa16(base + (10240 + row1 * PIT + c81) * 2,
              g_item_h + (size_t)(bn + row1) * FN + c81);
        cp_commit();
    }
#pragma unroll
    for (int ki = 0; ki < 4; ++ki) {
        if (ki < 3) {
            int k0 = (ki + 1) * 32, st = (ki + 1) & 1;
            cpa16(base + (st * 5120 + row0 * PIT + c80) * 2,
                  g_members_h + (size_t)(bm + row0) * FN + k0 + c80);
            cpa16(base + (st * 5120 + row1 * PIT + c81) * 2,
                  g_members_h + (size_t)(bm + row1) * FN + k0 + c81);
            cpa16(base + (10240 + st * 5120 + row0 * PIT + c80) * 2,
                  g_item_h + (size_t)(bn + row0) * FN + k0 + c80);
            cpa16(base + (10240 + st * 5120 + row1 * PIT + c81) * 2,
                  g_item_h + (size_t)(bn + row1) * FN + k0 + c81);
            cp_commit();
            cp_wait<1>();
        } else {
            cp_wait<0>();
        }
        __syncthreads();
        int st = ki & 1;
        uint32_t ab = base + st * 5120 * 2;
        uint32_t bb = base + (10240 + st * 5120) * 2;
#pragma unroll
        for (int ks = 0; ks < 2; ++ks) {
            int kl = ks * 16 + (q >> 1) * 8;
            uint32_t a[4][4], b[4][2];
#pragma unroll
            for (int mi = 0; mi < 4; ++mi) {
                int arow = wm * 64 + mi * 16 + (q & 1) * 8 + r;
                ldsm4(a[mi], ab + (arow * PIT + kl) * 2);
            }
#pragma unroll
            for (int j = 0; j < 2; ++j) {
                int brow = wn * 32 + j * 16 + (q & 1) * 8 + r;
                uint32_t t[4];
                ldsm4(t, bb + (brow * PIT + kl) * 2);
                b[j * 2][0] = t[0]; b[j * 2 + 1][0] = t[1];
                b[j * 2][1] = t[2]; b[j * 2 + 1][1] = t[3];
            }
#pragma unroll
            for (int mi = 0; mi < 4; ++mi)
#pragma unroll
                for (int ni = 0; ni < 4; ++ni) mma16(acc[mi][ni], a[mi], b[ni]);
        }
        __syncthreads();
    }
    // epilogue: exp -> smem staging + row sums
#pragma unroll
    for (int mi = 0; mi < 4; ++mi) {
        int r0 = wm * 64 + mi * 16 + qr;
        float s0 = 0.f, s1 = 0.f;
#pragma unroll
        for (int ni = 0; ni < 4; ++ni) {
            int lc = wn * 32 + ni * 8 + qc * 2;
            float e0 = pexp(acc[mi][ni][0]), e1 = pexp(acc[mi][ni][1]);
            float e2 = pexp(acc[mi][ni][2]), e3 = pexp(acc[mi][ni][3]);
            *(__half2*)&SM[r0 * 136 + lc] = __floats2half2_rn(e0, e1);
            *(__half2*)&SM[(r0 + 8) * 136 + lc] = __floats2half2_rn(e2, e3);
            s0 += e0 + e1; s1 += e2 + e3;
        }
        s0 += __shfl_xor_sync(0xffffffffu, s0, 1);
        s0 += __shfl_xor_sync(0xffffffffu, s0, 2);
        s1 += __shfl_xor_sync(0xffffffffu, s1, 1);
        s1 += __shfl_xor_sync(0xffffffffu, s1, 2);
        if (qc == 0) { rs[r0][wn] = s0; rs[r0 + 8][wn] = s1; }
    }
    __syncthreads();
    // coalesced copy-out: 2048 chunks of 16B, 8 per thread
#pragma unroll
    for (int it = 0; it < 8; ++it) {
        int ch = tid + it * 256;
        int row = ch >> 4, c8 = (ch & 15) * 8;
        uint4 v = *(const uint4*)&SM[row * 136 + c8];
        *(uint4*)(g_S + (size_t)(bm + row) * IN_ + bn + c8) = v;
    }
    if (tid < 128) {
        float s = rs[tid][0] + rs[tid][1] + rs[tid][2] + rs[tid][3];
        atomicAdd(&g_sum[bm + tid], s);
    }
}

__global__ void inv_bmat_k() {
    int t = blockIdx.x * blockDim.x + threadIdx.x;
    if (t >= MN * 16) return;
    int m = t >> 4;
    float sc = 4096.0f / g_sum[m];
    uint4 v = ((const uint4*)g_members_h)[t];
    __half2 s2 = __float2half2_rn(sc);
    uint4 o;
    o.x = h2u(__hmul2(*(__half2*)&v.x, s2));
    o.y = h2u(__hmul2(*(__half2*)&v.y, s2));
    o.z = h2u(__hmul2(*(__half2*)&v.z, s2));
    o.w = h2u(__hmul2(*(__half2*)&v.w, s2));
    ((uint4*)g_bmat)[t] = o;
}

// =============== GEMM2 (fp16 mma, split-K, cp.async 2-stage, red2) ============
#define PIT2 136
__global__ __launch_bounds__(256, 2) void attn2_k() {
    __shared__ __half Ssm[2][32 * PIT2];
    __shared__ __half Bsm[2][32 * PIT2];
    int bi = blockIdx.x * 128;
    int ms = blockIdx.y * MCH;
    int tid = threadIdx.x, lane = tid & 31, warp = tid >> 5;
    int wm = warp >> 2, wn = warp & 3;
    int qr = lane >> 2, qc = lane & 3;
    int q = lane >> 3, r = lane & 7;
    uint32_t sbase = s2u(Ssm), bbase = s2u(Bsm);
    int smm0 = tid >> 4, sc80 = (tid & 15) * 8;
    int smm1 = (tid + 256) >> 4, sc81 = ((tid + 256) & 15) * 8;
    float acc[4][4][4];
#pragma unroll
    for (int i = 0; i < 4; i++)
#pragma unroll
        for (int j = 0; j < 4; j++)
#pragma unroll
            for (int c = 0; c < 4; c++) acc[i][j][c] = 0.f;

    const int NIT = MCH / 32;
    {
        cpa16(sbase + (smm0 * PIT2 + sc80) * 2,
              g_S + (size_t)(ms + smm0) * IN_ + bi + sc80);
        cpa16(sbase + (smm1 * PIT2 + sc81) * 2,
              g_S + (size_t)(ms + smm1) * IN_ + bi + sc81);
        cpa16(bbase + (smm0 * PIT2 + sc80) * 2,
              g_bmat + (size_t)(ms + smm0) * FN + sc80);
        cpa16(bbase + (smm1 * PIT2 + sc81) * 2,
              g_bmat + (size_t)(ms + smm1) * FN + sc81);
        cp_commit();
    }
    for (int j = 0; j < NIT; ++j) {
        if (j + 1 < NIT) {
            int m0 = ms + (j + 1) * 32, st = (j + 1) & 1;
            cpa16(sbase + (st * 32 * PIT2 + smm0 * PIT2 + sc80) * 2,
                  g_S + (size_t)(m0 + smm0) * IN_ + bi + sc80);
            cpa16(sbase + (st * 32 * PIT2 + smm1 * PIT2 + sc81) * 2,
                  g_S + (size_t)(m0 + smm1) * IN_ + bi + sc81);
            cpa16(bbase + (st * 32 * PIT2 + smm0 * PIT2 + sc80) * 2,
                  g_bmat + (size_t)(m0 + smm0) * FN + sc80);
            cpa16(bbase + (st * 32 * PIT2 + smm1 * PIT2 + sc81) * 2,
                  g_bmat + (size_t)(m0 + smm1) * FN + sc81);
            cp_commit();
            cp_wait<1>();
        } else {
            cp_wait<0>();
        }
        __syncthreads();
        int st = j & 1;
        uint32_t sb = sbase + st * 32 * PIT2 * 2;
        uint32_t bb = bbase + st * 32 * PIT2 * 2;
#pragma unroll
        for (int ks = 0; ks < 2; ++ks) {
            int k0l = ks * 16;
            uint32_t a[4][4], b[4][2];
#pragma unroll
            for (int mi = 0; mi < 4; ++mi) {
                int row = k0l + (q >> 1) * 8 + r;
                int col = wm * 64 + mi * 16 + (q & 1) * 8;
                ldsm4t(a[mi], sb + (row * PIT2 + col) * 2);
            }
#pragma unroll
            for (int jn = 0; jn < 2; ++jn) {
                int row = k0l + (q & 1) * 8 + r;
                int col = wn * 32 + jn * 16 + (q >> 1) * 8;
                uint32_t t[4];
                ldsm4t(t, bb + (row * PIT2 + col) * 2);
                b[jn * 2][0] = t[0]; b[jn * 2][1] = t[1];
                b[jn * 2 + 1][0] = t[2]; b[jn * 2 + 1][1] = t[3];
            }
#pragma unroll
            for (int mi = 0; mi < 4; ++mi)
#pragma unroll
                for (int ni = 0; ni < 4; ++ni) mma16(acc[mi][ni], a[mi], b[ni]);
        }
        __syncthreads();
    }
#pragma unroll
    for (int mi = 0; mi < 4; ++mi) {
        int r0 = wm * 64 + mi * 16 + qr;
#pragma unroll
        for (int ni = 0; ni < 4; ++ni) {
            int col = wn * 32 + ni * 8 + qc * 2;
            red2(g_acc + (size_t)(bi + r0) * FN + col, acc[mi][ni][0], acc[mi][ni][1]);
            red2(g_acc + (size_t)(bi + r0 + 8) * FN + col, acc[mi][ni][2], acc[mi][ni][3]);
        }
    }
}

// =============== attitem = g_acc * item * 2^-12 ================================
__global__ void attn2_reduce_k(const float* __restrict__ item) {
    int t = blockIdx.x * blockDim.x + threadIdx.x;
    if (t >= IN_ * FN / 4) return;
    float4 s = ((const float4*)g_acc)[t];
    float4 e = ((const float4*)item)[t];
    const float c = 0.000244140625f;  // 2^-12
    s.x *= e.x * c; s.y *= e.y * c; s.z *= e.z * c; s.w *= e.w * c;
    ((float4*)g_attitem)[t] = s;
}

// =============== dual COO scatter: out1[r]+=v*X1[c]; out2[c]+=v*X2[r] ==========
__global__ void spmm_dual_k(const int* __restrict__ rows,
                            const int* __restrict__ cols,
                            const float* __restrict__ vals,
                            const float* __restrict__ X1, float* __restrict__ out1,
                            const float* __restrict__ X2, float* __restrict__ out2,
                            int nnz) {
    int w = (int)((blockIdx.x * 256u + threadIdx.x) >> 5);
    if (w >= nnz) return;
    int lane = threadIdx.x & 31;
    int r = rows[w], c = cols[w];
    float v = vals[w];
    float4 x1 = ((const float4*)(X1 + (size_t)c * FN))[lane];
    float4 x2 = ((const float4*)(X2 + (size_t)r * FN))[lane];
    red4(out1 + (size_t)r * FN + lane * 4, v * x1.x, v * x1.y, v * x1.z, v * x1.w);
    red4(out2 + (size_t)c * FN + lane * 4, v * x2.x, v * x2.y, v * x2.z, v * x2.w);
}

// =============== single COO scatter (att_g) ====================================
__global__ void spmm_k(const int* __restrict__ rows, const int* __restrict__ cols,
                       const float* __restrict__ vals, const float* __restrict__ X,
                       float* __restrict__ out, int nnz) {
    int w = (int)((blockIdx.x * 256u + threadIdx.x) >> 5);
    if (w >= nnz) return;
    int lane = threadIdx.x & 31;
    int r = rows[w], c = cols[w];
    float v = vals[w];
    float4 x = ((const float4*)(X + (size_t)c * FN))[lane];
    float* o = out + (size_t)r * FN + lane * 4;
    red4(o, v * x.x, v * x.y, v * x.z, v * x.w);
}

// =============== fused lin5 (fp16 mma, Bs cp.async 2-stage) ====================
// MODE 0 (user/item): xs = [e, a, a*e, b*e, b];  MODE 1 (group): [e, a, b*e, a*e, c]
template <int MODE>
__global__ __launch_bounds__(256, 2) void lin5_k(
    const float* __restrict__ E, const float* __restrict__ A,
    const float* __restrict__ B, const float* __restrict__ C4,
    const __half* __restrict__ Wh, const float* __restrict__ bias,
    float* __restrict__ out, int Md) {
    __shared__ __half raw[3][128 * 32];
    __shared__ __half As[128 * PIT];
    __shared__ __half Bs[2][128 * PIT];
    __shared__ float rs[128][4];
    __shared__ float bsum[128];
    int tid = threadIdx.x, lane = tid & 31, warp = tid >> 5;
    int wm = warp >> 2, wn = warp & 3;
    int qr = lane >> 2, qc = lane & 3;
    int q = lane >> 3, r = lane & 7;
    uint32_t abase = s2u(As), bbase = s2u(Bs);
    int bm = blockIdx.x * 128;
    int brow0 = tid >> 2, bc80 = (tid & 3) * 8;
    int brow1 = (tid + 256) >> 2, bc81 = ((tid + 256) & 3) * 8;
    if (tid < 128)
        bsum[tid] = bias[tid] + bias[128 + tid] + bias[256 + tid] +
                    bias[384 + tid] + bias[512 + tid];
    float acc[4][4][4];
#pragma unroll
    for (int i = 0; i < 4; i++)
#pragma unroll
        for (int j = 0; j < 4; j++)
#pragma unroll
            for (int c = 0; c < 4; c++) acc[i][j][c] = 0.f;

    // prefetch step 0's W tile (kblk=0, fb=0)
    {
        cpa16(bbase + (brow0 * PIT + bc80) * 2, Wh + (size_t)brow0 * FN + bc80);
        cpa16(bbase + (brow1 * PIT + bc81) * 2, Wh + (size_t)brow1 * FN + bc81);
        cp_commit();
    }
    for (int s = 0; s < 20; ++s) {
        int fbi = s / 5, kblk = s % 5, fb = fbi * 32;
        if (kblk == 0) {
            // load raw E/A/B tiles for this fbi
#pragma unroll
            for (int it = 0; it < 6; ++it) {
                int ch = tid + it * 256;
                int tilei = ch / 512, rem = ch & 511;
                int row = rem >> 2, c8 = (rem & 3) * 8;
                int m = bm + row;
                float4 v0 = {0.f, 0.f, 0.f, 0.f}, v1 = {0.f, 0.f, 0.f, 0.f};
                if (m < Md) {
                    const float* src = tilei == 0 ? E : (tilei == 1 ? A : B);
                    size_t off = (size_t)m * FN + fb + c8;
                    v0 = *(const float4*)(src + off);
                    v1 = *(const float4*)(src + off + 4);
                }
                *(uint4*)&raw[tilei][row * 32 + c8] = f8_to_h8(v0, v1);
            }
            __syncthreads();
        }
        // build As slab from raw tiles
#pragma unroll
        for (int it = 0; it < 2; ++it) {
            int ch = tid + it * 256;
            int row = ch >> 2, c8 = (ch & 3) * 8;
            uint4 o;
            if (kblk == 0) o = *(const uint4*)&raw[0][row * 32 + c8];
            else if (kblk == 1) o = *(const uint4*)&raw[1][row * 32 + c8];
            else if (kblk == 2)
                o = hmul8(*(const uint4*)&raw[MODE == 0 ? 1 : 2][row * 32 + c8],
                          *(const uint4*)&raw[0][row * 32 + c8]);
            else if (kblk == 3)
                o = hmul8(*(const uint4*)&raw[MODE == 0 ? 2 : 1][row * 32 + c8],
                          *(const uint4*)&raw[0][row * 32 + c8]);
            else {
                if (MODE == 0) o = *(const uint4*)&raw[2][row * 32 + c8];
                else {
                    int m = bm + row;
                    float4 v0 = {0.f, 0.f, 0.f, 0.f}, v1 = v0;
                    if (m < Md) {
                        size_t off = (size_t)m * FN + fb + c8;
                        v0 = *(const float4*)(C4 + off);
                        v1 = *(const float4*)(C4 + off + 4);
                    }
                    o = f8_to_h8(v0, v1);
                }
            }
            *(uint4*)&As[row * PIT + c8] = o;
        }
        // prefetch next step's W tile
        if (s < 19) {
            int nk = (s + 1) % 5, nfb = ((s + 1) / 5) * 32, st = (s + 1) & 1;
            cpa16(bbase + (st * 128 * PIT + brow0 * PIT + bc80) * 2,
                  Wh + (size_t)nk * 16384 + (size_t)brow0 * FN + nfb + bc80);
            cpa16(bbase + (st * 128 * PIT + brow1 * PIT + bc81) * 2,
                  Wh + (size_t)nk * 16384 + (size_t)brow1 * FN + nfb + bc81);
            cp_commit();
            cp_wait<1>();
        } else {
            cp_wait<0>();
        }
        __syncthreads();
        uint32_t bb = bbase + (s & 1) * 128 * PIT * 2;
#pragma unroll
        for (int ks = 0; ks < 2; ++ks) {
            int kl = ks * 16 + (q >> 1) * 8;
            uint32_t a[4][4], b[4][2];
#pragma unroll
            for (int mi = 0; mi < 4; ++mi) {
                int arow = wm * 64 + mi * 16 + (q & 1) * 8 + r;
                ldsm4(a[mi], abase + (arow * PIT + kl) * 2);
            }
#pragma unroll
            for (int j = 0; j < 2; ++j) {
                int brow = wn * 32 + j * 16 + (q & 1) * 8 + r;
                uint32_t t[4];
                ldsm4(t, bb + (brow * PIT + kl) * 2);
                b[j * 2][0] = t[0]; b[j * 2 + 1][0] = t[1];
                b[j * 2][1] = t[2]; b[j * 2 + 1][1] = t[3];
            }
#pragma unroll
            for (int mi = 0; mi < 4; ++mi)
#pragma unroll
                for (int ni = 0; ni < 4; ++ni) mma16(acc[mi][ni], a[mi], b[ni]);
        }
        __syncthreads();
    }
#pragma unroll
    for (int mi = 0; mi < 4; ++mi) {
        int r0 = wm * 64 + mi * 16 + qr;
        float s0 = 0.f, s1 = 0.f;
#pragma unroll
        for (int ni = 0; ni < 4; ++ni) {
            int col = wn * 32 + ni * 8 + qc * 2;
            float b0 = bsum[col], b1 = bsum[col + 1];
            float v0 = acc[mi][ni][0] + b0, v1 = acc[mi][ni][1] + b1;
            float v2 = acc[mi][ni][2] + b0, v3 = acc[mi][ni][3] + b1;
            v0 = v0 >= 0.f ? v0 : 0.01f * v0;
            v1 = v1 >= 0.f ? v1 : 0.01f * v1;
            v2 = v2 >= 0.f ? v2 : 0.01f * v2;
            v3 = v3 >= 0.f ? v3 : 0.01f * v3;
            acc[mi][ni][0] = v0; acc[mi][ni][1] = v1;
            acc[mi][ni][2] = v2; acc[mi][ni][3] = v3;
            s0 += v0 * v0 + v1 * v1;
            s1 += v2 * v2 + v3 * v3;
        }
        s0 += __shfl_xor_sync(0xffffffffu, s0, 1);
        s0 += __shfl_xor_sync(0xffffffffu, s0, 2);
        s1 += __shfl_xor_sync(0xffffffffu, s1, 1);
        s1 += __shfl_xor_sync(0xffffffffu, s1, 2);
        if (qc == 0) { rs[r0][wn] = s0; rs[r0 + 8][wn] = s1; }
    }
    __syncthreads();
#pragma unroll
    for (int mi = 0; mi < 4; ++mi) {
        int r0 = wm * 64 + mi * 16 + qr;
        float t0 = rs[r0][0] + rs[r0][1] + rs[r0][2] + rs[r0][3];
        float t1 = rs[r0 + 8][0] + rs[r0 + 8][1] + rs[r0 + 8][2] + rs[r0 + 8][3];
        float i0 = 1.0f / fmaxf(sqrtf(t0), 1e-12f);
        float i1 = 1.0f / fmaxf(sqrtf(t1), 1e-12f);
        int m0g = bm + r0, m1g = m0g + 8;
#pragma unroll
        for (int ni = 0; ni < 4; ++ni) {
            int col = wn * 32 + ni * 8 + qc * 2;
            if (m0g < Md) {
                float2 v = {acc[mi][ni][0] * i0, acc[mi][ni][1] * i0};
                *(float2*)(out + (size_t)m0g * FN + col) = v;
            }
            if (m1g < Md) {
                float2 v = {acc[mi][ni][2] * i1, acc[mi][ni][3] * i1};
                *(float2*)(out + (size_t)m1g * FN + col) = v;
            }
        }
    }
}

// =============== launch =========================================================
extern "C" void kernel_launch(void* const* d_in, const int* in_sizes, int n_in,
                              void* d_out, int out_size) {
    const float* group_emb = (const float*)d_in[0];
    const float* user_emb  = (const float*)d_in[1];
    const float* item_emb  = (const float*)d_in[2];
    const int*   member_idx = (const int*)d_in[3];
    const int*   rui_rows = (const int*)d_in[4];
    const int*   rui_cols = (const int*)d_in[5];
    const float* rui_vals = (const float*)d_in[6];
    const int*   rgu_rows = (const int*)d_in[7];
    const int*   rgu_cols = (const int*)d_in[8];
    const float* rgu_vals = (const float*)d_in[9];
    const int*   rgi_rows = (const int*)d_in[10];
    const int*   rgi_cols = (const int*)d_in[11];
    const float* rgi_vals = (const float*)d_in[12];
    const float* Wu = (const float*)d_in[13];
    const float* bu = (const float*)d_in[14];
    const float* Wi = (const float*)d_in[15];
    const float* bi = (const float*)d_in[16];
    const float* Wg = (const float*)d_in[17];
    const float* bg = (const float*)d_in[18];

    float* out = (float*)d_out;
    float* out_g = out;
    float* out_u = out + (size_t)GN * FN;
    float* out_i = out + (size_t)(GN + UN) * FN;

    void *p_rui_ei, *p_rgu_t, *p_rgi_t, *p_rui_t, *p_rgi_ei, *p_rgu_eu,
         *p_att_g, *p_attitem, *p_sum, *p_acc, *p_wu, *p_wi, *p_wg;
    cudaGetSymbolAddress(&p_rui_ei, g_rui_ei);
    cudaGetSymbolAddress(&p_rgu_t, g_rgu_t);
    cudaGetSymbolAddress(&p_rgi_t, g_rgi_t);
    cudaGetSymbolAddress(&p_rui_t, g_rui_t);
    cudaGetSymbolAddress(&p_rgi_ei, g_rgi_ei);
    cudaGetSymbolAddress(&p_rgu_eu, g_rgu_eu);
    cudaGetSymbolAddress(&p_att_g, g_att_g);
    cudaGetSymbolAddress(&p_attitem, g_attitem);
    cudaGetSymbolAddress(&p_sum, g_sum);
    cudaGetSymbolAddress(&p_acc, g_acc);
    cudaGetSymbolAddress(&p_wu, g_Wu_h);
    cudaGetSymbolAddress(&p_wi, g_Wi_h);
    cudaGetSymbolAddress(&p_wg, g_Wg_h);

    // fork at entry: chain B owns its own memsets + scatters
    cudaEventRecord(s_e0, 0);
    cudaStreamWaitEvent(s_b, s_e0, 0);
    cudaMemsetAsync(p_rui_ei, 0, sizeof(float) * (size_t)UN * FN, s_b);
    cudaMemsetAsync(p_rgu_t, 0, sizeof(float) * (size_t)UN * FN, s_b);
    cudaMemsetAsync(p_rgi_t, 0, sizeof(float) * (size_t)IN_ * FN, s_b);
    cudaMemsetAsync(p_rui_t, 0, sizeof(float) * (size_t)IN_ * FN, s_b);
    cudaMemsetAsync(p_rgi_ei, 0, sizeof(float) * (size_t)GN * FN, s_b);
    cudaMemsetAsync(p_rgu_eu, 0, sizeof(float) * (size_t)GN * FN, s_b);
    spmm_dual_k<<<(NNZ_RUI + 7) / 8, 256, 0, s_b>>>(
        rui_rows, rui_cols, rui_vals, item_emb, (float*)p_rui_ei,
        user_emb, (float*)p_rui_t, NNZ_RUI);
    spmm_dual_k<<<(NNZ_RGU + 7) / 8, 256, 0, s_b>>>(
        rgu_rows, rgu_cols, rgu_vals, user_emb, (float*)p_rgu_eu,
        group_emb, (float*)p_rgu_t, NNZ_RGU);
    spmm_dual_k<<<(NNZ_RGI + 7) / 8, 256, 0, s_b>>>(
        rgi_rows, rgi_cols, rgi_vals, item_emb, (float*)p_rgi_ei,
        group_emb, (float*)p_rgi_t, NNZ_RGI);

    // origin: small memsets + conversions, then attention chain
    cudaMemsetAsync(p_att_g, 0, sizeof(float) * (size_t)GN * FN);
    cudaMemsetAsync(p_sum, 0, sizeof(float) * MN);
    cudaMemsetAsync(p_acc, 0, sizeof(float) * (size_t)IN_ * FN);
    fat0_k<<<1144, 256>>>(user_emb, member_idx, item_emb, Wu, Wi, Wg);
    cudaEventRecord(s_e2, 0);  // weights + fp16 operands ready

    // chain B tail: lin5 user/item need weights (s_e2) + own scatters
    cudaStreamWaitEvent(s_b, s_e2, 0);
    lin5_k<0><<<(UN + 127) / 128, 256, 0, s_b>>>(
        user_emb, (const float*)p_rui_ei, (const float*)p_rgu_t, nullptr,
        (const __half*)p_wu, bu, out_u, UN);
    lin5_k<0><<<IN_ / 128, 256, 0, s_b>>>(
        item_emb, (const float*)p_rui_t, (const float*)p_rgi_t, nullptr,
        (const __half*)p_wi, bi, out_i, IN_);
    cudaEventRecord(s_e1, s_b);

    // chain A on origin stream: attention path
    gemm_s_k<<<dim3(IN_ / 128, MN / 128), 256>>>();
    inv_bmat_k<<<512, 256>>>();
    attn2_k<<<dim3(IN_ / 128, SPLIT), 256>>>();
    attn2_reduce_k<<<(IN_ * FN / 4 + 255) / 256, 256>>>(item_emb);
    spmm_k<<<(NNZ_RGI + 7) / 8, 256>>>(rgi_rows, rgi_cols, rgi_vals,
                                       (const float*)p_attitem,
                                       (float*)p_att_g, NNZ_RGI);

    // join: group lin5 needs chain B's rgi_ei / rgu_eu
    cudaStreamWaitEvent(0, s_e1, 0);
    lin5_k<1><<<GN / 128, 256>>>(group_emb, (const float*)p_rgi_ei,
                                 (const float*)p_rgu_eu, (const float*)p_att_g,
                                 (const __half*)p_wg, bg, out_g, GN);
}